// round 1
// baseline (speedup 1.0000x reference)
#include <cuda_runtime.h>
#include <math.h>

#define HH 108
#define NCAP 100000
#define ECAP 1600000
#define GCAP 1024
#define SC_T 256
#define SC_I 8
#define SC_CH (SC_T * SC_I)  // 2048

// -------- device scratch (no allocation allowed) --------
__device__ float g_h[NCAP * HH];
__device__ float g_z[NCAP * HH];
__device__ float g_c[NCAP * HH];
__device__ float g_bb[NCAP * HH];
__device__ int   g_deg[NCAP];
__device__ int   g_rowptr[NCAP + 1];
__device__ int   g_cursor[NCAP];
__device__ int   g_col[ECAP];
__device__ int   g_part[256];
__device__ float g_hg[GCAP * HH];
__device__ float g_cnt[GCAP];

// ---------------- CSR build ----------------
__global__ void zero_deg_kernel(int n) {
    int i = blockIdx.x * blockDim.x + threadIdx.x;
    if (i < n) g_deg[i] = 0;
}

__global__ void hist_kernel(const int* __restrict__ dst, int e) {
    int i = blockIdx.x * blockDim.x + threadIdx.x;
    if (i < e) atomicAdd(&g_deg[dst[i]], 1);
}

__global__ void scan1_kernel(int n) {
    __shared__ int sh[SC_T];
    int t = threadIdx.x, b = blockIdx.x;
    int base = b * SC_CH + t * SC_I;
    int v[SC_I];
    int run = 0;
#pragma unroll
    for (int j = 0; j < SC_I; j++) {
        int idx = base + j;
        int x = (idx < n) ? g_deg[idx] : 0;
        run += x;
        v[j] = run;
    }
    sh[t] = run;
    __syncthreads();
    for (int off = 1; off < SC_T; off <<= 1) {
        int x = (t >= off) ? sh[t - off] : 0;
        __syncthreads();
        sh[t] += x;
        __syncthreads();
    }
    int excl = sh[t] - run;
#pragma unroll
    for (int j = 0; j < SC_I; j++) {
        int idx = base + j;
        if (idx < n) g_rowptr[1 + idx] = excl + v[j];
    }
    if (t == SC_T - 1) g_part[b] = sh[t];
}

__global__ void scan2_kernel(int nb) {
    if (threadIdx.x == 0 && blockIdx.x == 0) {
        int run = 0;
        for (int i = 0; i < nb; i++) {
            int x = g_part[i];
            g_part[i] = run;
            run += x;
        }
    }
}

__global__ void scan3_kernel(int n) {
    int idx = blockIdx.x * blockDim.x + threadIdx.x;
    if (idx < n) {
        int val = g_rowptr[1 + idx] + g_part[idx / SC_CH];
        g_rowptr[1 + idx] = val;
        if (idx + 1 < n) g_cursor[idx + 1] = val;
    }
    if (idx == 0) { g_rowptr[0] = 0; g_cursor[0] = 0; }
}

__global__ void fillcsr_kernel(const int* __restrict__ src, const int* __restrict__ dst, int e) {
    int i = blockIdx.x * blockDim.x + threadIdx.x;
    if (i < e) {
        int d = dst[i];
        int pos = atomicAdd(&g_cursor[d], 1);
        g_col[pos] = src[i];
    }
}

// ---------------- GEMM: out[n,108] = act( [X1|X2][n,K1+K2] @ W[K,108] + bias ) ----------------
// block = 216 threads (27 x 8), 64 rows per block, thread tile 8 rows x 4 cols.
__global__ void gemm_kernel(const float* __restrict__ X1, int K1,
                            const float* __restrict__ X2, int K2,
                            const float* __restrict__ W,
                            const float* __restrict__ bias,
                            float* __restrict__ out, int n, int relu) {
    extern __shared__ float smem[];
    const int K = K1 + K2;
    float* Ws = smem;              // K * 108
    float* Xs = smem + K * HH;     // 64 * 32
    const int tid = threadIdx.x;

    for (int i = tid; i < K * HH; i += 216) Ws[i] = W[i];

    const int tx = tid % 27;
    const int ty = tid / 27;
    const int row0 = blockIdx.x * 64;

    float acc[8][4];
#pragma unroll
    for (int r = 0; r < 8; r++)
#pragma unroll
        for (int q = 0; q < 4; q++) acc[r][q] = 0.f;

    for (int kc = 0; kc < K; kc += 32) {
        const int kw = min(32, K - kc);
        __syncthreads();
        for (int i = tid; i < 2048; i += 216) {
            int r = i >> 5, k = i & 31;
            int row = row0 + r;
            float v = 0.f;
            int kk = kc + k;
            if (row < n && k < kw)
                v = (kk < K1) ? X1[(size_t)row * K1 + kk]
                              : X2[(size_t)row * K2 + (kk - K1)];
            Xs[i] = v;
        }
        __syncthreads();
        for (int k = 0; k < kw; k++) {
            const float4 w = *(const float4*)(Ws + (kc + k) * HH + tx * 4);
#pragma unroll
            for (int r = 0; r < 8; r++) {
                const float a = Xs[(ty + r * 8) * 32 + k];
                acc[r][0] = fmaf(a, w.x, acc[r][0]);
                acc[r][1] = fmaf(a, w.y, acc[r][1]);
                acc[r][2] = fmaf(a, w.z, acc[r][2]);
                acc[r][3] = fmaf(a, w.w, acc[r][3]);
            }
        }
    }

    const float b0 = bias[tx * 4], b1 = bias[tx * 4 + 1],
                b2 = bias[tx * 4 + 2], b3 = bias[tx * 4 + 3];
#pragma unroll
    for (int r = 0; r < 8; r++) {
        int row = row0 + ty + r * 8;
        if (row < n) {
            float4 o;
            o.x = acc[r][0] + b0;
            o.y = acc[r][1] + b1;
            o.z = acc[r][2] + b2;
            o.w = acc[r][3] + b3;
            if (relu) {
                o.x = fmaxf(o.x, 0.f); o.y = fmaxf(o.y, 0.f);
                o.z = fmaxf(o.z, 0.f); o.w = fmaxf(o.w, 0.f);
            }
            *(float4*)(out + (size_t)row * HH + tx * 4) = o;
        }
    }
}

// ---------------- mean aggregation over CSR (warp per node) ----------------
__global__ void aggregate_kernel(const float* __restrict__ z, float* __restrict__ c, int n) {
    int w = (blockIdx.x * blockDim.x + threadIdx.x) >> 5;
    int lane = threadIdx.x & 31;
    if (w >= n) return;
    int s = g_rowptr[w], epos = g_rowptr[w + 1];
    float a0 = 0.f, a1 = 0.f, a2 = 0.f, a3 = 0.f;
    for (int i = s; i < epos; i++) {
        int u = g_col[i];
        const float* zr = z + (size_t)u * HH;
        a0 += zr[lane];
        a1 += zr[lane + 32];
        a2 += zr[lane + 64];
        if (lane < 12) a3 += zr[lane + 96];
    }
    float inv = 1.f / (float)max(epos - s, 1);
    float* cr = c + (size_t)w * HH;
    cr[lane] = a0 * inv;
    cr[lane + 32] = a1 * inv;
    cr[lane + 64] = a2 * inv;
    if (lane < 12) cr[lane + 96] = a3 * inv;
}

// ---------------- L2 normalize + relu + residual (warp per node) ----------------
__global__ void norm_res_kernel(const float* __restrict__ b, float* __restrict__ h, int n) {
    int w = (blockIdx.x * blockDim.x + threadIdx.x) >> 5;
    int lane = threadIdx.x & 31;
    if (w >= n) return;
    const float* br = b + (size_t)w * HH;
    float v0 = br[lane], v1 = br[lane + 32], v2 = br[lane + 64];
    float v3 = (lane < 12) ? br[lane + 96] : 0.f;
    float ss = v0 * v0 + v1 * v1 + v2 * v2 + v3 * v3;
#pragma unroll
    for (int o = 16; o; o >>= 1) ss += __shfl_xor_sync(0xFFFFFFFFu, ss, o);
    float scale = 1.f / fmaxf(sqrtf(ss), 1e-12f);
    float* hr = h + (size_t)w * HH;
    hr[lane]      += fmaxf(v0 * scale, 0.f);
    hr[lane + 32] += fmaxf(v1 * scale, 0.f);
    hr[lane + 64] += fmaxf(v2 * scale, 0.f);
    if (lane < 12) hr[lane + 96] += fmaxf(v3 * scale, 0.f);
}

// ---------------- graph readout ----------------
__global__ void readout_zero_kernel(int g) {
    int i = blockIdx.x * blockDim.x + threadIdx.x;
    if (i < g * HH) g_hg[i] = 0.f;
    if (i < g) g_cnt[i] = 0.f;
}

__global__ void readout_kernel(const float* __restrict__ h, const int* __restrict__ gids, int n) {
    int w = (blockIdx.x * blockDim.x + threadIdx.x) >> 5;
    int lane = threadIdx.x & 31;
    if (w >= n) return;
    int g = gids[w];
    const float* hr = h + (size_t)w * HH;
    atomicAdd(&g_hg[g * HH + lane], hr[lane]);
    atomicAdd(&g_hg[g * HH + lane + 32], hr[lane + 32]);
    atomicAdd(&g_hg[g * HH + lane + 64], hr[lane + 64]);
    if (lane < 12) atomicAdd(&g_hg[g * HH + lane + 96], hr[lane + 96]);
    if (lane == 0) atomicAdd(&g_cnt[g], 1.f);
}

__global__ void finalize_kernel(float* __restrict__ out, int total) {
    int i = blockIdx.x * blockDim.x + threadIdx.x;
    if (i < total) out[i] = g_hg[i] / fmaxf(g_cnt[i / HH], 1.f);
}

// ---------------- launch ----------------
extern "C" void kernel_launch(void* const* d_in, const int* in_sizes, int n_in,
                              void* d_out, int out_size) {
    const float* nodes_feat = (const float*)d_in[0];
    const float* W_emb  = (const float*)d_in[4];
    const float* b_emb  = (const float*)d_in[5];
    const float* pool_W = (const float*)d_in[6];
    const float* pool_b = (const float*)d_in[7];
    const float* app_W  = (const float*)d_in[8];
    const float* app_b  = (const float*)d_in[9];
    const int* src  = (const int*)d_in[10];
    const int* dst  = (const int*)d_in[11];
    const int* gids = (const int*)d_in[12];

    const int n = in_sizes[12];              // graph_ids length = N
    const int e = in_sizes[10];              // src length = E
    const int in_dim = in_sizes[4] / HH;     // W_emb [IN,108]
    const int n_layers = in_sizes[6] / (HH * HH);
    const int G = out_size / HH;

    float *hP, *zP, *cP, *bP;
    cudaGetSymbolAddress((void**)&hP, g_h);
    cudaGetSymbolAddress((void**)&zP, g_z);
    cudaGetSymbolAddress((void**)&cP, g_c);
    cudaGetSymbolAddress((void**)&bP, g_bb);

    cudaFuncSetAttribute(gemm_kernel, cudaFuncAttributeMaxDynamicSharedMemorySize,
                         (216 * HH + 64 * 32) * (int)sizeof(float));

    // ---- CSR by dst ----
    zero_deg_kernel<<<(n + 255) / 256, 256>>>(n);
    hist_kernel<<<(e + 255) / 256, 256>>>(dst, e);
    int nb = (n + SC_CH - 1) / SC_CH;
    scan1_kernel<<<nb, SC_T>>>(n);
    scan2_kernel<<<1, 32>>>(nb);
    scan3_kernel<<<(n + 255) / 256, 256>>>(n);
    fillcsr_kernel<<<(e + 255) / 256, 256>>>(src, dst, e);

    // ---- embedding: h = nodes_feat @ W_emb + b_emb ----
    {
        int K = in_dim;
        size_t sm = (size_t)(K * HH + 64 * 32) * sizeof(float);
        gemm_kernel<<<(n + 63) / 64, 216, sm>>>(nodes_feat, K, (const float*)0, 0,
                                                W_emb, b_emb, hP, n, 0);
    }

    int warp_blocks = ((n * 32) + 255) / 256;

    for (int l = 0; l < n_layers; l++) {
        const float* pW = pool_W + (size_t)l * HH * HH;
        const float* pb = pool_b + (size_t)l * HH;
        const float* aW = app_W + (size_t)l * 2 * HH * HH;
        const float* ab = app_b + (size_t)l * HH;

        // z = relu(h @ pool_W + pool_b)
        {
            size_t sm = (size_t)(HH * HH + 64 * 32) * sizeof(float);
            gemm_kernel<<<(n + 63) / 64, 216, sm>>>(hP, HH, (const float*)0, 0,
                                                    pW, pb, zP, n, 1);
        }
        // c = mean_{u in N(v)} z[u]
        aggregate_kernel<<<warp_blocks, 256>>>(zP, cP, n);
        // b = [h|c] @ app_W + app_b
        {
            size_t sm = (size_t)(2 * HH * HH + 64 * 32) * sizeof(float);
            gemm_kernel<<<(n + 63) / 64, 216, sm>>>(hP, HH, cP, HH,
                                                    aW, ab, bP, n, 0);
        }
        // h += relu(b / max(||b||,1e-12))
        norm_res_kernel<<<warp_blocks, 256>>>(bP, hP, n);
    }

    // ---- readout: per-graph mean ----
    readout_zero_kernel<<<(G * HH + 255) / 256, 256>>>(G);
    readout_kernel<<<warp_blocks, 256>>>(hP, gids, n);
    finalize_kernel<<<(out_size + 255) / 256, 256>>>((float*)d_out, out_size);
}

// round 3
// speedup vs baseline: 1.4965x; 1.4965x over previous
#include <cuda_runtime.h>
#include <cuda_bf16.h>
#include <math.h>
#include <stdint.h>

#define HH 108
#define NCAP 100000
#define ECAP 1600000
#define GCAP 1024
#define SC_T 256
#define SC_I 8
#define SC_CH (SC_T * SC_I)  // 2048

// -------- device scratch (no allocation allowed) --------
__device__ float g_h[NCAP * HH];
__device__ float g_z[NCAP * HH];
__device__ float g_c[NCAP * HH];
__device__ int   g_deg[NCAP];
__device__ int   g_rowptr[NCAP + 1];
__device__ int   g_cursor[NCAP];
__device__ int   g_col[ECAP];
__device__ int   g_part[256];
__device__ float g_hg[GCAP * HH];
__device__ float g_cnt[GCAP];

// ================= warp-MMA helpers (sm_80+ path; compiles for compute_103) ====
__device__ __forceinline__ uint32_t smem_to_u32(const void* smem_ptr) {
    uint32_t addr;
    asm("{ .reg .u64 tmp; cvta.to.shared.u64 tmp, %1; cvt.u32.u64 %0, tmp; }"
        : "=r"(addr) : "l"(smem_ptr));
    return addr;
}
__device__ __forceinline__ void ldm_x4(uint32_t* r, uint32_t addr) {
    asm volatile("ldmatrix.sync.aligned.m8n8.x4.shared.b16 {%0,%1,%2,%3}, [%4];"
        : "=r"(r[0]), "=r"(r[1]), "=r"(r[2]), "=r"(r[3]) : "r"(addr));
}
__device__ __forceinline__ void ldm_x2(uint32_t* r, uint32_t addr) {
    asm volatile("ldmatrix.sync.aligned.m8n8.x2.shared.b16 {%0,%1}, [%2];"
        : "=r"(r[0]), "=r"(r[1]) : "r"(addr));
}
__device__ __forceinline__ void mma_bf16(float* c, const uint32_t* a, const uint32_t* b) {
    asm volatile(
        "mma.sync.aligned.m16n8k16.row.col.f32.bf16.bf16.f32 "
        "{%0,%1,%2,%3}, {%4,%5,%6,%7}, {%8,%9}, {%0,%1,%2,%3};"
        : "+f"(c[0]), "+f"(c[1]), "+f"(c[2]), "+f"(c[3])
        : "r"(a[0]), "r"(a[1]), "r"(a[2]), "r"(a[3]), "r"(b[0]), "r"(b[1]));
}
#define SWZ128(b) ((b) ^ (((b) >> 3) & 0x70))

// ================= smem layout for gemm_tc (D-stage overlaps A/B) =============
#define SM_BIAS 32       // 112 floats
#define SM_INV  480      // 128 floats
#define SM_AH   1024     // 128 x 64 bf16, SW128 rows of 128B -> 16384 B
#define SM_AL   17408
#define SM_BH   33792    // 112 n-rows x 64 k bf16 -> 14336 B
#define SM_BL   48128
#define SM_D    SM_AH    // 128 x 116 f32 = 59392 B, reused after MMA loop
#define D_PITCH 116
#define SM_TOTAL 62464

// ================= CSR build =================
__global__ void zero_deg_kernel(int n) {
    int i = blockIdx.x * blockDim.x + threadIdx.x;
    if (i < n) g_deg[i] = 0;
}
__global__ void hist_kernel(const int* __restrict__ dst, int e) {
    int i = blockIdx.x * blockDim.x + threadIdx.x;
    if (i < e) atomicAdd(&g_deg[dst[i]], 1);
}
__global__ void scan1_kernel(int n) {
    __shared__ int sh[SC_T];
    int t = threadIdx.x, b = blockIdx.x;
    int base = b * SC_CH + t * SC_I;
    int v[SC_I];
    int run = 0;
#pragma unroll
    for (int j = 0; j < SC_I; j++) {
        int idx = base + j;
        int x = (idx < n) ? g_deg[idx] : 0;
        run += x;
        v[j] = run;
    }
    sh[t] = run;
    __syncthreads();
    for (int off = 1; off < SC_T; off <<= 1) {
        int x = (t >= off) ? sh[t - off] : 0;
        __syncthreads();
        sh[t] += x;
        __syncthreads();
    }
    int excl = sh[t] - run;
#pragma unroll
    for (int j = 0; j < SC_I; j++) {
        int idx = base + j;
        if (idx < n) g_rowptr[1 + idx] = excl + v[j];
    }
    if (t == SC_T - 1) g_part[b] = sh[t];
}
__global__ void scan2_kernel(int nb) {
    if (threadIdx.x == 0 && blockIdx.x == 0) {
        int run = 0;
        for (int i = 0; i < nb; i++) {
            int x = g_part[i];
            g_part[i] = run;
            run += x;
        }
    }
}
__global__ void scan3_kernel(int n) {
    int idx = blockIdx.x * blockDim.x + threadIdx.x;
    if (idx < n) {
        int val = g_rowptr[1 + idx] + g_part[idx / SC_CH];
        g_rowptr[1 + idx] = val;
        if (idx + 1 < n) g_cursor[idx + 1] = val;
    }
    if (idx == 0) { g_rowptr[0] = 0; g_cursor[0] = 0; }
}
__global__ void fillcsr_kernel(const int* __restrict__ src, const int* __restrict__ dst, int e) {
    int i = blockIdx.x * blockDim.x + threadIdx.x;
    if (i < e) {
        int d = dst[i];
        int pos = atomicAdd(&g_cursor[d], 1);
        g_col[pos] = src[i];
    }
}

// ================= tensor-core GEMM (split-bf16, 3-term, mma.sync) ============
// out[n,108] = act( [X1|X2] @ W[K,108] + bias )
// mode 0: plain store; mode 1: relu store; mode 2: L2-norm rows + relu + hres +=
__global__ __launch_bounds__(256, 2)
void gemm_tc(const float* __restrict__ X1, int K1,
             const float* __restrict__ X2, int K2,
             const float* __restrict__ W,
             const float* __restrict__ bias,
             float* __restrict__ out,
             float* __restrict__ hres,
             int n, int K, int mode) {
    extern __shared__ char sm[];
    const uint32_t sb = smem_to_u32(sm);
    const int tid = threadIdx.x;
    const int wid = tid >> 5;
    const int lane = tid & 31;
    const int row0 = blockIdx.x * 128;
    float* bias_s = (float*)(sm + SM_BIAS);
    float* inv_s  = (float*)(sm + SM_INV);
    float* Ds     = (float*)(sm + SM_D);

    if (tid < 112) bias_s[tid] = (tid < HH) ? bias[tid] : 0.f;

    float acc[14][4];
#pragma unroll
    for (int nt = 0; nt < 14; nt++)
#pragma unroll
        for (int q = 0; q < 4; q++) acc[nt][q] = 0.f;

    const int warp_r0 = wid * 16;
    const int a_row = warp_r0 + (lane & 15);
    const int a_kb  = (lane >> 4) * 16;        // k-byte half for x4
    const int b_row = lane & 7;
    const int b_kb  = ((lane >> 3) & 1) * 16;  // k-byte half for x2

    const int NC = (K + 63) >> 6;
    for (int c = 0; c < NC; c++) {
        const int kc = c << 6;
        __syncthreads();  // previous iter's ldmatrix / D-stage done
        // ---- fill A (128 rows x 64 k) hi/lo bf16, swizzled ----
        for (int j = tid; j < 128 * 32; j += 256) {
            int row = j >> 5;
            int kp = j & 31;
            int kk = kc + kp * 2;
            int grow = row0 + row;
            float x0 = 0.f, x1 = 0.f;
            if (grow < n) {
                if (kk < K)
                    x0 = (kk < K1) ? X1[grow * K1 + kk] : X2[grow * K2 + kk - K1];
                if (kk + 1 < K)
                    x1 = (kk + 1 < K1) ? X1[grow * K1 + kk + 1] : X2[grow * K2 + kk + 1 - K1];
            }
            __nv_bfloat16 h0 = __float2bfloat16(x0), h1 = __float2bfloat16(x1);
            float l0 = x0 - __bfloat162float(h0), l1 = x1 - __bfloat162float(h1);
            __nv_bfloat16 g0 = __float2bfloat16(l0), g1 = __float2bfloat16(l1);
            uint32_t hp = ((uint32_t)__bfloat16_as_ushort(h1) << 16) | __bfloat16_as_ushort(h0);
            uint32_t lp = ((uint32_t)__bfloat16_as_ushort(g1) << 16) | __bfloat16_as_ushort(g0);
            uint32_t off = SWZ128((uint32_t)(row * 128 + kp * 4));
            *(uint32_t*)(sm + SM_AH + off) = hp;
            *(uint32_t*)(sm + SM_AL + off) = lp;
        }
        // ---- fill B (112 n-rows x 64 k) = W^T hi/lo bf16, swizzled ----
        for (int j = tid; j < 112 * 64; j += 256) {
            int k = j / 112;
            int nn = j - k * 112;
            int kk = kc + k;
            float w = (nn < HH && kk < K) ? W[kk * HH + nn] : 0.f;
            __nv_bfloat16 h0 = __float2bfloat16(w);
            float l = w - __bfloat162float(h0);
            __nv_bfloat16 g0 = __float2bfloat16(l);
            uint32_t off = SWZ128((uint32_t)(nn * 128 + k * 2));
            *(unsigned short*)(sm + SM_BH + off) = __bfloat16_as_ushort(h0);
            *(unsigned short*)(sm + SM_BL + off) = __bfloat16_as_ushort(g0);
        }
        __syncthreads();
        // ---- MMA: 4 k-steps x 14 n-tiles x 3 terms ----
#pragma unroll
        for (int ks = 0; ks < 4; ks++) {
            uint32_t aloc = SWZ128((uint32_t)(a_row * 128 + a_kb + ks * 32));
            uint32_t ah[4], al[4];
            ldm_x4(ah, sb + SM_AH + aloc);
            ldm_x4(al, sb + SM_AL + aloc);
            uint32_t bloc = SWZ128((uint32_t)(b_row * 128 + b_kb + ks * 32));
#pragma unroll
            for (int nt = 0; nt < 14; nt++) {
                uint32_t bh[2], bl[2];
                ldm_x2(bh, sb + SM_BH + bloc + nt * 1024);
                ldm_x2(bl, sb + SM_BL + bloc + nt * 1024);
                mma_bf16(acc[nt], ah, bh);
                mma_bf16(acc[nt], al, bh);
                mma_bf16(acc[nt], ah, bl);
            }
        }
    }
    __syncthreads();  // all warps done reading A/B before D-stage overwrites them

    // ---- epilogue: accumulators -> smem stage (+bias) ----
    {
        int er = warp_r0 + (lane >> 2);
        int ec = (lane & 3) * 2;
#pragma unroll
        for (int nt = 0; nt < 14; nt++) {
            int col = nt * 8 + ec;
            float b0 = bias_s[col], b1 = bias_s[col + 1];
            float2 lo = make_float2(acc[nt][0] + b0, acc[nt][1] + b1);
            float2 hi = make_float2(acc[nt][2] + b0, acc[nt][3] + b1);
            *(float2*)(Ds + er * D_PITCH + col) = lo;
            *(float2*)(Ds + (er + 8) * D_PITCH + col) = hi;
        }
    }
    __syncwarp();

    if (mode == 2) {
        // per-row L2 norm over first 108 cols (rows owned by this warp)
        for (int rr = 0; rr < 16; rr++) {
            int row = warp_r0 + rr;
            const float* dr = Ds + row * D_PITCH;
            float v0 = dr[lane], v1 = dr[lane + 32], v2 = dr[lane + 64];
            float v3 = (lane < 12) ? dr[lane + 96] : 0.f;
            float ss = v0 * v0 + v1 * v1 + v2 * v2 + v3 * v3;
#pragma unroll
            for (int o = 16; o; o >>= 1) ss += __shfl_xor_sync(0xFFFFFFFFu, ss, o);
            if (lane == 0) inv_s[row] = 1.f / fmaxf(sqrtf(ss), 1e-12f);
        }
    }
    __syncthreads();

    // ---- coalesced writeback ----
    for (int i = tid; i < 128 * 27; i += 256) {
        int row = i / 27;
        int v = i - row * 27;
        int grow = row0 + row;
        if (grow >= n) continue;
        float4 d4 = *(const float4*)(Ds + row * D_PITCH + v * 4);
        if (mode == 0) {
            *(float4*)(out + grow * HH + v * 4) = d4;
        } else if (mode == 1) {
            d4.x = fmaxf(d4.x, 0.f); d4.y = fmaxf(d4.y, 0.f);
            d4.z = fmaxf(d4.z, 0.f); d4.w = fmaxf(d4.w, 0.f);
            *(float4*)(out + grow * HH + v * 4) = d4;
        } else {
            float s = inv_s[row];
            float4 h4 = *(const float4*)(hres + grow * HH + v * 4);
            h4.x += fmaxf(d4.x * s, 0.f);
            h4.y += fmaxf(d4.y * s, 0.f);
            h4.z += fmaxf(d4.z * s, 0.f);
            h4.w += fmaxf(d4.w * s, 0.f);
            *(float4*)(hres + grow * HH + v * 4) = h4;
        }
    }
}

// ================= mean aggregation over CSR (warp per node) =================
__global__ void aggregate_kernel(const float* __restrict__ z, float* __restrict__ c, int n) {
    int w = (blockIdx.x * blockDim.x + threadIdx.x) >> 5;
    int lane = threadIdx.x & 31;
    if (w >= n) return;
    int s = g_rowptr[w], epos = g_rowptr[w + 1];
    float a0 = 0.f, a1 = 0.f, a2 = 0.f, a3 = 0.f;
    for (int i = s; i < epos; i++) {
        int u = g_col[i];
        const float* zr = z + (size_t)u * HH;
        a0 += zr[lane];
        a1 += zr[lane + 32];
        a2 += zr[lane + 64];
        if (lane < 12) a3 += zr[lane + 96];
    }
    float inv = 1.f / (float)max(epos - s, 1);
    float* cr = c + (size_t)w * HH;
    cr[lane] = a0 * inv;
    cr[lane + 32] = a1 * inv;
    cr[lane + 64] = a2 * inv;
    if (lane < 12) cr[lane + 96] = a3 * inv;
}

// ================= graph readout =================
__global__ void readout_zero_kernel(int g) {
    int i = blockIdx.x * blockDim.x + threadIdx.x;
    if (i < g * HH) g_hg[i] = 0.f;
    if (i < g) g_cnt[i] = 0.f;
}
__global__ void readout_kernel(const float* __restrict__ h, const int* __restrict__ gids, int n) {
    int w = (blockIdx.x * blockDim.x + threadIdx.x) >> 5;
    int lane = threadIdx.x & 31;
    if (w >= n) return;
    int g = gids[w];
    const float* hr = h + (size_t)w * HH;
    atomicAdd(&g_hg[g * HH + lane], hr[lane]);
    atomicAdd(&g_hg[g * HH + lane + 32], hr[lane + 32]);
    atomicAdd(&g_hg[g * HH + lane + 64], hr[lane + 64]);
    if (lane < 12) atomicAdd(&g_hg[g * HH + lane + 96], hr[lane + 96]);
    if (lane == 0) atomicAdd(&g_cnt[g], 1.f);
}
__global__ void finalize_kernel(float* __restrict__ out, int total) {
    int i = blockIdx.x * blockDim.x + threadIdx.x;
    if (i < total) out[i] = g_hg[i] / fmaxf(g_cnt[i / HH], 1.f);
}

// ================= launch =================
extern "C" void kernel_launch(void* const* d_in, const int* in_sizes, int n_in,
                              void* d_out, int out_size) {
    const float* nodes_feat = (const float*)d_in[0];
    const float* W_emb  = (const float*)d_in[4];
    const float* b_emb  = (const float*)d_in[5];
    const float* pool_W = (const float*)d_in[6];
    const float* pool_b = (const float*)d_in[7];
    const float* app_W  = (const float*)d_in[8];
    const float* app_b  = (const float*)d_in[9];
    const int* src  = (const int*)d_in[10];
    const int* dst  = (const int*)d_in[11];
    const int* gids = (const int*)d_in[12];

    const int n = in_sizes[12];
    const int e = in_sizes[10];
    const int in_dim = in_sizes[4] / HH;
    const int n_layers = in_sizes[6] / (HH * HH);
    const int G = out_size / HH;

    float *hP, *zP, *cP;
    cudaGetSymbolAddress((void**)&hP, g_h);
    cudaGetSymbolAddress((void**)&zP, g_z);
    cudaGetSymbolAddress((void**)&cP, g_c);

    cudaFuncSetAttribute(gemm_tc, cudaFuncAttributeMaxDynamicSharedMemorySize, SM_TOTAL);

    // ---- CSR by dst ----
    zero_deg_kernel<<<(n + 255) / 256, 256>>>(n);
    hist_kernel<<<(e + 255) / 256, 256>>>(dst, e);
    int nb = (n + SC_CH - 1) / SC_CH;
    scan1_kernel<<<nb, SC_T>>>(n);
    scan2_kernel<<<1, 32>>>(nb);
    scan3_kernel<<<(n + 255) / 256, 256>>>(n);
    fillcsr_kernel<<<(e + 255) / 256, 256>>>(src, dst, e);

    const int gB = (n + 127) / 128;

    // ---- embedding: h = nodes_feat @ W_emb + b_emb ----
    gemm_tc<<<gB, 256, SM_TOTAL>>>(nodes_feat, in_dim, (const float*)0, 0,
                                   W_emb, b_emb, hP, (float*)0, n, in_dim, 0);

    int warp_blocks = ((n * 32) + 255) / 256;

    for (int l = 0; l < n_layers; l++) {
        const float* pW = pool_W + (size_t)l * HH * HH;
        const float* pb = pool_b + (size_t)l * HH;
        const float* aW = app_W + (size_t)l * 2 * HH * HH;
        const float* ab = app_b + (size_t)l * HH;

        // z = relu(h @ pool_W + pool_b)
        gemm_tc<<<gB, 256, SM_TOTAL>>>(hP, HH, (const float*)0, 0,
                                       pW, pb, zP, (float*)0, n, HH, 1);
        // c = mean_{u in N(v)} z[u]
        aggregate_kernel<<<warp_blocks, 256>>>(zP, cP, n);
        // h += relu(l2norm([h|c] @ app_W + app_b))  (fused)
        gemm_tc<<<gB, 256, SM_TOTAL>>>(hP, HH, cP, HH,
                                       aW, ab, (float*)0, hP, n, 2 * HH, 2);
    }

    // ---- readout: per-graph mean ----
    readout_zero_kernel<<<(G * HH + 255) / 256, 256>>>(G);
    readout_kernel<<<warp_blocks, 256>>>(hP, gids, n);
    finalize_kernel<<<(out_size + 255) / 256, 256>>>((float*)d_out, out_size);
}

// round 4
// speedup vs baseline: 1.5651x; 1.0459x over previous
#include <cuda_runtime.h>
#include <cuda_bf16.h>
#include <math.h>
#include <stdint.h>

#define HH 108
#define HU 54              // u32 per split row
#define NCAP 100000
#define ECAP 1600000
#define GCAP 1024
#define SC_T 256
#define SC_I 8
#define SC_CH (SC_T * SC_I)  // 2048

// -------- device scratch (no allocation allowed) --------
__device__ float    g_h[NCAP * HH];
__device__ float    g_z[NCAP * HH];
__device__ uint32_t g_hh[NCAP * HU];   // h hi bf16 pairs
__device__ uint32_t g_hl[NCAP * HU];   // h lo bf16 pairs
__device__ uint32_t g_ch[NCAP * HU];   // c hi
__device__ uint32_t g_cl[NCAP * HU];   // c lo
__device__ uint32_t g_wh[65536];       // prepped weights hi (u32 pairs)
__device__ uint32_t g_wl[65536];
__device__ int   g_deg[NCAP];
__device__ int   g_rowptr[NCAP + 1];
__device__ int   g_cursor[NCAP];
__device__ int   g_col[ECAP];
__device__ int   g_part[256];
__device__ float g_hg[GCAP * HH];
__device__ float g_cnt[GCAP];

// ================= helpers =================
__device__ __forceinline__ uint32_t smem_to_u32(const void* smem_ptr) {
    uint32_t addr;
    asm("{ .reg .u64 tmp; cvta.to.shared.u64 tmp, %1; cvt.u32.u64 %0, tmp; }"
        : "=r"(addr) : "l"(smem_ptr));
    return addr;
}
__device__ __forceinline__ void ldm_x4(uint32_t* r, uint32_t addr) {
    asm volatile("ldmatrix.sync.aligned.m8n8.x4.shared.b16 {%0,%1,%2,%3}, [%4];"
        : "=r"(r[0]), "=r"(r[1]), "=r"(r[2]), "=r"(r[3]) : "r"(addr));
}
__device__ __forceinline__ void ldm_x2(uint32_t* r, uint32_t addr) {
    asm volatile("ldmatrix.sync.aligned.m8n8.x2.shared.b16 {%0,%1}, [%2];"
        : "=r"(r[0]), "=r"(r[1]) : "r"(addr));
}
__device__ __forceinline__ void mma_bf16(float* c, const uint32_t* a, const uint32_t* b) {
    asm volatile(
        "mma.sync.aligned.m16n8k16.row.col.f32.bf16.bf16.f32 "
        "{%0,%1,%2,%3}, {%4,%5,%6,%7}, {%8,%9}, {%0,%1,%2,%3};"
        : "+f"(c[0]), "+f"(c[1]), "+f"(c[2]), "+f"(c[3])
        : "r"(a[0]), "r"(a[1]), "r"(a[2]), "r"(a[3]), "r"(b[0]), "r"(b[1]));
}
#define SWZ128(b) ((b) ^ (((b) >> 3) & 0x70))

__device__ __forceinline__ void split2(float x, float y, uint32_t& hp, uint32_t& lp) {
    __nv_bfloat16 hx = __float2bfloat16(x), hy = __float2bfloat16(y);
    float lx = x - __bfloat162float(hx), ly = y - __bfloat162float(hy);
    hp = ((uint32_t)__bfloat16_as_ushort(hy) << 16) | __bfloat16_as_ushort(hx);
    lp = ((uint32_t)__bfloat16_as_ushort(__float2bfloat16(ly)) << 16)
       | __bfloat16_as_ushort(__float2bfloat16(lx));
}

// ================= smem layout for gemm_tc (D-stage overlaps A/B) =============
#define SM_BIAS 32
#define SM_INV  480
#define SM_AH   1024     // 128 x 64 bf16, 128B rows -> 16384 B
#define SM_AL   17408
#define SM_BH   33792    // 112 n-rows x 64 k bf16 -> 14336 B
#define SM_BL   48128
#define SM_D    SM_AH    // 128 x 116 f32, reused after MMA loop
#define D_PITCH 116
#define SM_TOTAL 62464

// ================= weight prep: fp32 W[k][108] -> padded split pairs ==========
// layout (u32 units): emb [112 x KPe/2] | pool_l [112 x 64] | app_l [112 x 128]
__global__ void prep_w(const float* __restrict__ W_emb, int Kemb, int KPe,
                       const float* __restrict__ pool_W,
                       const float* __restrict__ app_W, int n_layers, int total) {
    int idx = blockIdx.x * blockDim.x + threadIdx.x;
    if (idx >= total) return;
    const float* Wp = 0;
    int K = 0, KP = 0, rel = idx, off = 0;
    int sz = 112 * (KPe >> 1);
    if (idx < sz) { Wp = W_emb; K = Kemb; KP = KPe; rel = idx; }
    else {
        off = sz;
        for (int l = 0; l < n_layers && !Wp; l++) {
            if (idx < off + 112 * 64) { Wp = pool_W + l * HH * HH; K = HH; KP = 128; rel = idx - off; }
            off += 112 * 64;
        }
        for (int l = 0; l < n_layers && !Wp; l++) {
            if (idx < off + 112 * 128) { Wp = app_W + l * 2 * HH * HH; K = 2 * HH; KP = 256; rel = idx - off; }
            off += 112 * 128;
        }
        if (!Wp) return;
    }
    int nn = rel / (KP >> 1);
    int kp = rel - nn * (KP >> 1);
    int k0 = kp * 2;
    float w0 = (nn < HH && k0 < K) ? Wp[k0 * HH + nn] : 0.f;
    float w1 = (nn < HH && k0 + 1 < K) ? Wp[(k0 + 1) * HH + nn] : 0.f;
    uint32_t hp, lp;
    split2(w0, w1, hp, lp);
    g_wh[idx] = hp;
    g_wl[idx] = lp;
}

// ================= CSR build =================
__global__ void zero_deg_kernel(int n) {
    int i = blockIdx.x * blockDim.x + threadIdx.x;
    if (i < n) g_deg[i] = 0;
}
__global__ void hist_kernel(const int* __restrict__ dst, int e) {
    int i = blockIdx.x * blockDim.x + threadIdx.x;
    if (i < e) atomicAdd(&g_deg[dst[i]], 1);
}
__global__ void scan1_kernel(int n) {
    __shared__ int sh[SC_T];
    int t = threadIdx.x, b = blockIdx.x;
    int base = b * SC_CH + t * SC_I;
    int v[SC_I];
    int run = 0;
#pragma unroll
    for (int j = 0; j < SC_I; j++) {
        int idx = base + j;
        int x = (idx < n) ? g_deg[idx] : 0;
        run += x;
        v[j] = run;
    }
    sh[t] = run;
    __syncthreads();
    for (int off = 1; off < SC_T; off <<= 1) {
        int x = (t >= off) ? sh[t - off] : 0;
        __syncthreads();
        sh[t] += x;
        __syncthreads();
    }
    int excl = sh[t] - run;
#pragma unroll
    for (int j = 0; j < SC_I; j++) {
        int idx = base + j;
        if (idx < n) g_rowptr[1 + idx] = excl + v[j];
    }
    if (t == SC_T - 1) g_part[b] = sh[t];
}
__global__ void scan2_kernel(int nb) {
    __shared__ int sh[256];
    int t = threadIdx.x;
    int v = (t < nb) ? g_part[t] : 0;
    sh[t] = v;
    __syncthreads();
    for (int off = 1; off < 256; off <<= 1) {
        int x = (t >= off) ? sh[t - off] : 0;
        __syncthreads();
        sh[t] += x;
        __syncthreads();
    }
    if (t < nb) g_part[t] = sh[t] - v;  // exclusive
}
__global__ void scan3_kernel(int n) {
    int idx = blockIdx.x * blockDim.x + threadIdx.x;
    if (idx < n) {
        int val = g_rowptr[1 + idx] + g_part[idx / SC_CH];
        g_rowptr[1 + idx] = val;
        if (idx + 1 < n) g_cursor[idx + 1] = val;
    }
    if (idx == 0) { g_rowptr[0] = 0; g_cursor[0] = 0; }
}
__global__ void fillcsr_kernel(const int* __restrict__ src, const int* __restrict__ dst, int e) {
    int i = blockIdx.x * blockDim.x + threadIdx.x;
    if (i < e) {
        int d = dst[i];
        int pos = atomicAdd(&g_cursor[d], 1);
        g_col[pos] = src[i];
    }
}

// ================= tensor-core GEMM (split-bf16, 3-term, mma.sync) ============
// out[n,108] = act( A @ W + bias ); A from fp32 (X1f) or pre-split pairs.
// mode 0: store fp32 + split; mode 1: relu store fp32; mode 2: L2-norm+relu+residual (+split)
__global__ __launch_bounds__(256, 2)
void gemm_tc(const float* __restrict__ X1f,
             const uint32_t* __restrict__ Ah1, const uint32_t* __restrict__ Al1, int K1,
             const uint32_t* __restrict__ Ah2, const uint32_t* __restrict__ Al2, int K2,
             const uint32_t* __restrict__ Wh, const uint32_t* __restrict__ Wl, int wstride,
             const float* __restrict__ bias,
             float* __restrict__ out, float* __restrict__ hres,
             uint32_t* __restrict__ outH, uint32_t* __restrict__ outL,
             int n, int K, int mode) {
    extern __shared__ char sm[];
    const uint32_t sb = smem_to_u32(sm);
    const int tid = threadIdx.x;
    const int wid = tid >> 5;
    const int lane = tid & 31;
    const int row0 = blockIdx.x * 128;
    float* bias_s = (float*)(sm + SM_BIAS);
    float* inv_s  = (float*)(sm + SM_INV);
    float* Ds     = (float*)(sm + SM_D);

    if (tid < 112) bias_s[tid] = (tid < HH) ? bias[tid] : 0.f;

    float acc[14][4];
#pragma unroll
    for (int nt = 0; nt < 14; nt++)
#pragma unroll
        for (int q = 0; q < 4; q++) acc[nt][q] = 0.f;

    const int warp_r0 = wid * 16;
    const int a_row = warp_r0 + (lane & 15);
    const int a_kb  = (lane >> 4) * 16;
    const int b_row = lane & 7;
    const int b_kb  = ((lane >> 3) & 1) * 16;
    const int K1u = K1 >> 1, K2u = K2 >> 1;

    const int NC = (K + 63) >> 6;
    for (int c = 0; c < NC; c++) {
        const int kc = c << 6;
        __syncthreads();
        // ---- fill A (128 rows x 64 k), swizzled ----
        if (X1f) {
            for (int j = tid; j < 128 * 32; j += 256) {
                int row = j >> 5, kp = j & 31;
                int kk = kc + kp * 2;
                int grow = row0 + row;
                float x0 = 0.f, x1 = 0.f;
                if (grow < n) {
                    if (kk < K) x0 = X1f[grow * K + kk];
                    if (kk + 1 < K) x1 = X1f[grow * K + kk + 1];
                }
                uint32_t hp, lp;
                split2(x0, x1, hp, lp);
                uint32_t off = SWZ128((uint32_t)(row * 128 + kp * 4));
                *(uint32_t*)(sm + SM_AH + off) = hp;
                *(uint32_t*)(sm + SM_AL + off) = lp;
            }
        } else {
            for (int j = tid; j < 128 * 32; j += 256) {
                int row = j >> 5, kp = j & 31;
                int kk = kc + kp * 2;
                int grow = row0 + row;
                uint32_t hp = 0, lp = 0;
                if (grow < n && kk < K) {
                    if (kk < K1) {
                        int idx = grow * K1u + (kk >> 1);
                        hp = Ah1[idx]; lp = Al1[idx];
                    } else {
                        int idx = grow * K2u + ((kk - K1) >> 1);
                        hp = Ah2[idx]; lp = Al2[idx];
                    }
                }
                uint32_t off = SWZ128((uint32_t)(row * 128 + kp * 4));
                *(uint32_t*)(sm + SM_AH + off) = hp;
                *(uint32_t*)(sm + SM_AL + off) = lp;
            }
        }
        // ---- fill B from prepped weights (112 x 64), swizzled ----
        for (int j = tid; j < 112 * 32; j += 256) {
            int nn = j >> 5, kp = j & 31;
            int idx = nn * wstride + (kc >> 1) + kp;
            uint32_t off = SWZ128((uint32_t)(nn * 128 + kp * 4));
            *(uint32_t*)(sm + SM_BH + off) = Wh[idx];
            *(uint32_t*)(sm + SM_BL + off) = Wl[idx];
        }
        __syncthreads();
        // ---- MMA: 4 k-steps x 14 n-tiles x 3 terms ----
#pragma unroll
        for (int ks = 0; ks < 4; ks++) {
            uint32_t aloc = SWZ128((uint32_t)(a_row * 128 + a_kb + ks * 32));
            uint32_t ah[4], al[4];
            ldm_x4(ah, sb + SM_AH + aloc);
            ldm_x4(al, sb + SM_AL + aloc);
            uint32_t bloc = SWZ128((uint32_t)(b_row * 128 + b_kb + ks * 32));
#pragma unroll
            for (int nt = 0; nt < 14; nt++) {
                uint32_t bh[2], bl[2];
                ldm_x2(bh, sb + SM_BH + bloc + nt * 1024);
                ldm_x2(bl, sb + SM_BL + bloc + nt * 1024);
                mma_bf16(acc[nt], ah, bh);
                mma_bf16(acc[nt], al, bh);
                mma_bf16(acc[nt], ah, bl);
            }
        }
    }
    __syncthreads();

    // ---- epilogue: accumulators -> smem stage (+bias) ----
    {
        int er = warp_r0 + (lane >> 2);
        int ec = (lane & 3) * 2;
#pragma unroll
        for (int nt = 0; nt < 14; nt++) {
            int col = nt * 8 + ec;
            float b0 = bias_s[col], b1 = bias_s[col + 1];
            float2 lo = make_float2(acc[nt][0] + b0, acc[nt][1] + b1);
            float2 hi = make_float2(acc[nt][2] + b0, acc[nt][3] + b1);
            *(float2*)(Ds + er * D_PITCH + col) = lo;
            *(float2*)(Ds + (er + 8) * D_PITCH + col) = hi;
        }
    }
    __syncwarp();

    if (mode == 2) {
        for (int rr = 0; rr < 16; rr++) {
            int row = warp_r0 + rr;
            const float* dr = Ds + row * D_PITCH;
            float v0 = dr[lane], v1 = dr[lane + 32], v2 = dr[lane + 64];
            float v3 = (lane < 12) ? dr[lane + 96] : 0.f;
            float ss = v0 * v0 + v1 * v1 + v2 * v2 + v3 * v3;
#pragma unroll
            for (int o = 16; o; o >>= 1) ss += __shfl_xor_sync(0xFFFFFFFFu, ss, o);
            if (lane == 0) inv_s[row] = 1.f / fmaxf(sqrtf(ss), 1e-12f);
        }
    }
    __syncthreads();

    // ---- coalesced writeback ----
    for (int i = tid; i < 128 * 27; i += 256) {
        int row = i / 27;
        int v = i - row * 27;
        int grow = row0 + row;
        if (grow >= n) continue;
        float4 d4 = *(const float4*)(Ds + row * D_PITCH + v * 4);
        if (mode == 0) {
            *(float4*)(out + grow * HH + v * 4) = d4;
        } else if (mode == 1) {
            d4.x = fmaxf(d4.x, 0.f); d4.y = fmaxf(d4.y, 0.f);
            d4.z = fmaxf(d4.z, 0.f); d4.w = fmaxf(d4.w, 0.f);
            *(float4*)(out + grow * HH + v * 4) = d4;
        } else {
            float s = inv_s[row];
            float4 h4 = *(const float4*)(hres + grow * HH + v * 4);
            h4.x += fmaxf(d4.x * s, 0.f);
            h4.y += fmaxf(d4.y * s, 0.f);
            h4.z += fmaxf(d4.z * s, 0.f);
            h4.w += fmaxf(d4.w * s, 0.f);
            *(float4*)(hres + grow * HH + v * 4) = h4;
            d4 = h4;
        }
        if ((mode == 0 || mode == 2) && outH) {
            uint32_t hp0, lp0, hp1, lp1;
            split2(d4.x, d4.y, hp0, lp0);
            split2(d4.z, d4.w, hp1, lp1);
            outH[grow * HU + v * 2] = hp0;
            outH[grow * HU + v * 2 + 1] = hp1;
            outL[grow * HU + v * 2] = lp0;
            outL[grow * HU + v * 2 + 1] = lp1;
        }
    }
}

// ===== mean aggregation over CSR (warp/node, float4, 2-edge unroll) -> split c
__global__ void aggregate_kernel(const float* __restrict__ z,
                                 uint32_t* __restrict__ ch, uint32_t* __restrict__ cl, int n) {
    int w = (blockIdx.x * blockDim.x + threadIdx.x) >> 5;
    int lane = threadIdx.x & 31;
    if (w >= n || lane >= 27) return;
    int s = g_rowptr[w], e = g_rowptr[w + 1];
    float4 a0 = make_float4(0.f, 0.f, 0.f, 0.f);
    float4 a1 = make_float4(0.f, 0.f, 0.f, 0.f);
    int i = s;
    for (; i + 1 < e; i += 2) {
        const float4 v0 = ((const float4*)(z + (size_t)g_col[i] * HH))[lane];
        const float4 v1 = ((const float4*)(z + (size_t)g_col[i + 1] * HH))[lane];
        a0.x += v0.x; a0.y += v0.y; a0.z += v0.z; a0.w += v0.w;
        a1.x += v1.x; a1.y += v1.y; a1.z += v1.z; a1.w += v1.w;
    }
    if (i < e) {
        const float4 v0 = ((const float4*)(z + (size_t)g_col[i] * HH))[lane];
        a0.x += v0.x; a0.y += v0.y; a0.z += v0.z; a0.w += v0.w;
    }
    float inv = 1.f / (float)max(e - s, 1);
    float cx = (a0.x + a1.x) * inv, cy = (a0.y + a1.y) * inv;
    float cz = (a0.z + a1.z) * inv, cw = (a0.w + a1.w) * inv;
    uint32_t hp0, lp0, hp1, lp1;
    split2(cx, cy, hp0, lp0);
    split2(cz, cw, hp1, lp1);
    ch[w * HU + lane * 2] = hp0;
    ch[w * HU + lane * 2 + 1] = hp1;
    cl[w * HU + lane * 2] = lp0;
    cl[w * HU + lane * 2 + 1] = lp1;
}

// ================= graph readout =================
__global__ void readout_zero_kernel(int g) {
    int i = blockIdx.x * blockDim.x + threadIdx.x;
    if (i < g * HH) g_hg[i] = 0.f;
    if (i < g) g_cnt[i] = 0.f;
}
__global__ void readout_kernel(const float* __restrict__ h, const int* __restrict__ gids, int n) {
    int w = (blockIdx.x * blockDim.x + threadIdx.x) >> 5;
    int lane = threadIdx.x & 31;
    if (w >= n) return;
    int g = gids[w];
    const float* hr = h + (size_t)w * HH;
    atomicAdd(&g_hg[g * HH + lane], hr[lane]);
    atomicAdd(&g_hg[g * HH + lane + 32], hr[lane + 32]);
    atomicAdd(&g_hg[g * HH + lane + 64], hr[lane + 64]);
    if (lane < 12) atomicAdd(&g_hg[g * HH + lane + 96], hr[lane + 96]);
    if (lane == 0) atomicAdd(&g_cnt[g], 1.f);
}
__global__ void finalize_kernel(float* __restrict__ out, int total) {
    int i = blockIdx.x * blockDim.x + threadIdx.x;
    if (i < total) out[i] = g_hg[i] / fmaxf(g_cnt[i / HH], 1.f);
}

// ================= launch =================
extern "C" void kernel_launch(void* const* d_in, const int* in_sizes, int n_in,
                              void* d_out, int out_size) {
    const float* nodes_feat = (const float*)d_in[0];
    const float* W_emb  = (const float*)d_in[4];
    const float* b_emb  = (const float*)d_in[5];
    const float* pool_W = (const float*)d_in[6];
    const float* pool_b = (const float*)d_in[7];
    const float* app_W  = (const float*)d_in[8];
    const float* app_b  = (const float*)d_in[9];
    const int* src  = (const int*)d_in[10];
    const int* dst  = (const int*)d_in[11];
    const int* gids = (const int*)d_in[12];

    const int n = in_sizes[12];
    const int e = in_sizes[10];
    const int in_dim = in_sizes[4] / HH;
    const int n_layers = in_sizes[6] / (HH * HH);
    const int G = out_size / HH;

    float *hP, *zP;
    uint32_t *hhP, *hlP, *chP, *clP, *whP, *wlP;
    cudaGetSymbolAddress((void**)&hP, g_h);
    cudaGetSymbolAddress((void**)&zP, g_z);
    cudaGetSymbolAddress((void**)&hhP, g_hh);
    cudaGetSymbolAddress((void**)&hlP, g_hl);
    cudaGetSymbolAddress((void**)&chP, g_ch);
    cudaGetSymbolAddress((void**)&clP, g_cl);
    cudaGetSymbolAddress((void**)&whP, g_wh);
    cudaGetSymbolAddress((void**)&wlP, g_wl);

    cudaFuncSetAttribute(gemm_tc, cudaFuncAttributeMaxDynamicSharedMemorySize, SM_TOTAL);

    // weight layout (u32 units)
    const int KPe = ((in_dim + 63) / 64) * 64;
    const int u_emb = 112 * (KPe >> 1);
    const int u_pool = 112 * 64;
    const int u_app = 112 * 128;
    const int w_total = u_emb + n_layers * (u_pool + u_app);

    prep_w<<<(w_total + 255) / 256, 256>>>(W_emb, in_dim, KPe, pool_W, app_W, n_layers, w_total);

    // ---- CSR by dst ----
    zero_deg_kernel<<<(n + 255) / 256, 256>>>(n);
    hist_kernel<<<(e + 255) / 256, 256>>>(dst, e);
    int nb = (n + SC_CH - 1) / SC_CH;
    scan1_kernel<<<nb, SC_T>>>(n);
    scan2_kernel<<<1, 256>>>(nb);
    scan3_kernel<<<(n + 255) / 256, 256>>>(n);
    fillcsr_kernel<<<(e + 255) / 256, 256>>>(src, dst, e);

    const int gB = (n + 127) / 128;
    int warp_blocks = ((n * 32) + 255) / 256;

    // ---- embedding: h = nodes_feat @ W_emb + b_emb (fp32 A path) ----
    gemm_tc<<<gB, 256, SM_TOTAL>>>(nodes_feat,
                                   (const uint32_t*)0, (const uint32_t*)0, in_dim,
                                   (const uint32_t*)0, (const uint32_t*)0, 0,
                                   whP, wlP, KPe >> 1,
                                   b_emb, hP, (float*)0, hhP, hlP, n, in_dim, 0);

    for (int l = 0; l < n_layers; l++) {
        const float* pb = pool_b + (size_t)l * HH;
        const float* ab = app_b + (size_t)l * HH;
        const uint32_t* pWh = whP + u_emb + l * u_pool;
        const uint32_t* pWl = wlP + u_emb + l * u_pool;
        const uint32_t* aWh = whP + u_emb + n_layers * u_pool + l * u_app;
        const uint32_t* aWl = wlP + u_emb + n_layers * u_pool + l * u_app;

        // z = relu(h @ pool_W + pool_b)
        gemm_tc<<<gB, 256, SM_TOTAL>>>((const float*)0,
                                       hhP, hlP, HH,
                                       (const uint32_t*)0, (const uint32_t*)0, 0,
                                       pWh, pWl, 64,
                                       pb, zP, (float*)0, (uint32_t*)0, (uint32_t*)0,
                                       n, HH, 1);
        // c = mean_{u in N(v)} z[u]  (written pre-split)
        aggregate_kernel<<<warp_blocks, 256>>>(zP, chP, clP, n);
        // h += relu(l2norm([h|c] @ app_W + app_b)); split-write h unless last layer
        int last = (l == n_layers - 1);
        gemm_tc<<<gB, 256, SM_TOTAL>>>((const float*)0,
                                       hhP, hlP, HH,
                                       chP, clP, HH,
                                       aWh, aWl, 128,
                                       ab, (float*)0, hP,
                                       last ? (uint32_t*)0 : hhP,
                                       last ? (uint32_t*)0 : hlP,
                                       n, 2 * HH, 2);
    }

    // ---- readout: per-graph mean ----
    readout_zero_kernel<<<(G * HH + 255) / 256, 256>>>(G);
    readout_kernel<<<warp_blocks, 256>>>(hP, gids, n);
    finalize_kernel<<<(out_size + 255) / 256, 256>>>((float*)d_out, out_size);
}

// round 5
// speedup vs baseline: 1.6027x; 1.0240x over previous
#include <cuda_runtime.h>
#include <cuda_fp16.h>
#include <math.h>
#include <stdint.h>

#define HH 108
#define HU 54              // u32 per split row
#define NCAP 100000
#define ECAP 1600000
#define GCAP 1024
#define SC_T 256
#define SC_I 8
#define SC_CH (SC_T * SC_I)  // 2048

// -------- device scratch (no allocation allowed) --------
__device__ float    g_h[NCAP * HH];
__device__ float    g_z[NCAP * HH];
__device__ uint32_t g_hh[NCAP * HU];   // h hi fp16 pairs
__device__ uint32_t g_hl[NCAP * HU];   // h lo fp16 pairs
__device__ uint32_t g_ch[NCAP * HU];   // c hi
__device__ uint32_t g_cl[NCAP * HU];   // c lo
__device__ uint32_t g_wh[65536];       // prepped weights hi (u32 pairs)
__device__ int   g_deg[NCAP];
__device__ int   g_rowptr[NCAP + 1];
__device__ int   g_cursor[NCAP];
__device__ int   g_col[ECAP];
__device__ int   g_part[256];
__device__ float g_hg[GCAP * HH];
__device__ float g_cnt[GCAP];

// ================= helpers =================
__device__ __forceinline__ uint32_t smem_to_u32(const void* smem_ptr) {
    uint32_t addr;
    asm("{ .reg .u64 tmp; cvta.to.shared.u64 tmp, %1; cvt.u32.u64 %0, tmp; }"
        : "=r"(addr) : "l"(smem_ptr));
    return addr;
}
__device__ __forceinline__ void ldm_x4(uint32_t* r, uint32_t addr) {
    asm volatile("ldmatrix.sync.aligned.m8n8.x4.shared.b16 {%0,%1,%2,%3}, [%4];"
        : "=r"(r[0]), "=r"(r[1]), "=r"(r[2]), "=r"(r[3]) : "r"(addr));
}
__device__ __forceinline__ void ldm_x2(uint32_t* r, uint32_t addr) {
    asm volatile("ldmatrix.sync.aligned.m8n8.x2.shared.b16 {%0,%1}, [%2];"
        : "=r"(r[0]), "=r"(r[1]) : "r"(addr));
}
__device__ __forceinline__ void mma_fp16(float* c, const uint32_t* a, const uint32_t* b) {
    asm volatile(
        "mma.sync.aligned.m16n8k16.row.col.f32.f16.f16.f32 "
        "{%0,%1,%2,%3}, {%4,%5,%6,%7}, {%8,%9}, {%0,%1,%2,%3};"
        : "+f"(c[0]), "+f"(c[1]), "+f"(c[2]), "+f"(c[3])
        : "r"(a[0]), "r"(a[1]), "r"(a[2]), "r"(a[3]), "r"(b[0]), "r"(b[1]));
}
#define SWZ128(b) ((b) ^ (((b) >> 3) & 0x70))

// fp16 split: x = hi + lo, hi = rn(x)
__device__ __forceinline__ void split2h(float x, float y, uint32_t& hp, uint32_t& lp) {
    __half hx = __float2half_rn(x), hy = __float2half_rn(y);
    float lx = x - __half2float(hx), ly = y - __half2float(hy);
    __half gx = __float2half_rn(lx), gy = __float2half_rn(ly);
    hp = ((uint32_t)__half_as_ushort(hy) << 16) | __half_as_ushort(hx);
    lp = ((uint32_t)__half_as_ushort(gy) << 16) | __half_as_ushort(gx);
}
__device__ __forceinline__ uint32_t pack_h(float x, float y) {
    return ((uint32_t)__half_as_ushort(__float2half_rn(y)) << 16)
         | __half_as_ushort(__float2half_rn(x));
}

// ================= smem layout for gemm_tc (D-stage overlaps A/B) =============
#define SM_BIAS 32
#define SM_INV  480
#define SM_AH   1024     // 128 x 64 fp16, 128B rows -> 16384 B
#define SM_AL   17408
#define SM_BH   33792    // 112 n-rows x 64 k fp16 -> 14336 B
#define SM_D    SM_AH    // 128 x 116 f32, reused after MMA loop
#define D_PITCH 116
#define SM_TOTAL 60416

// ================= weight prep: fp32 W[k][108] -> padded split pairs ==========
// layout (u32 units): emb [112 x KPe/2] | pool_l [112 x 64] | app_l [112 x 128]
// hi pairs in g_wh; lo of W is folded INTO hi? no: 2-term scheme drops B-lo entirely,
// so only hi needed for B. (A carries the correction term.)
__global__ void prep_w(const float* __restrict__ W_emb, int Kemb, int KPe,
                       const float* __restrict__ pool_W,
                       const float* __restrict__ app_W, int n_layers, int total) {
    int idx = blockIdx.x * blockDim.x + threadIdx.x;
    if (idx >= total) return;
    const float* Wp = 0;
    int K = 0, KP = 0, rel = idx, off = 0;
    int sz = 112 * (KPe >> 1);
    if (idx < sz) { Wp = W_emb; K = Kemb; KP = KPe; rel = idx; }
    else {
        off = sz;
        for (int l = 0; l < n_layers && !Wp; l++) {
            if (idx < off + 112 * 64) { Wp = pool_W + l * HH * HH; K = HH; KP = 128; rel = idx - off; }
            off += 112 * 64;
        }
        for (int l = 0; l < n_layers && !Wp; l++) {
            if (idx < off + 112 * 128) { Wp = app_W + l * 2 * HH * HH; K = 2 * HH; KP = 256; rel = idx - off; }
            off += 112 * 128;
        }
        if (!Wp) return;
    }
    int nn = rel / (KP >> 1);
    int kp = rel - nn * (KP >> 1);
    int k0 = kp * 2;
    float w0 = (nn < HH && k0 < K) ? Wp[k0 * HH + nn] : 0.f;
    float w1 = (nn < HH && k0 + 1 < K) ? Wp[(k0 + 1) * HH + nn] : 0.f;
    g_wh[idx] = pack_h(w0, w1);
}

// ================= CSR build =================
__global__ void zero_deg_kernel(int n) {
    int i = blockIdx.x * blockDim.x + threadIdx.x;
    if (i < n) g_deg[i] = 0;
}
__global__ void hist_kernel(const int* __restrict__ dst, int e) {
    int i = blockIdx.x * blockDim.x + threadIdx.x;
    if (i < e) atomicAdd(&g_deg[dst[i]], 1);
}
__global__ void scan1_kernel(int n) {
    __shared__ int sh[SC_T];
    int t = threadIdx.x, b = blockIdx.x;
    int base = b * SC_CH + t * SC_I;
    int v[SC_I];
    int run = 0;
#pragma unroll
    for (int j = 0; j < SC_I; j++) {
        int idx = base + j;
        int x = (idx < n) ? g_deg[idx] : 0;
        run += x;
        v[j] = run;
    }
    sh[t] = run;
    __syncthreads();
    for (int off = 1; off < SC_T; off <<= 1) {
        int x = (t >= off) ? sh[t - off] : 0;
        __syncthreads();
        sh[t] += x;
        __syncthreads();
    }
    int excl = sh[t] - run;
#pragma unroll
    for (int j = 0; j < SC_I; j++) {
        int idx = base + j;
        if (idx < n) g_rowptr[1 + idx] = excl + v[j];
    }
    if (t == SC_T - 1) g_part[b] = sh[t];
}
__global__ void scan2_kernel(int nb) {
    __shared__ int sh[256];
    int t = threadIdx.x;
    int v = (t < nb) ? g_part[t] : 0;
    sh[t] = v;
    __syncthreads();
    for (int off = 1; off < 256; off <<= 1) {
        int x = (t >= off) ? sh[t - off] : 0;
        __syncthreads();
        sh[t] += x;
        __syncthreads();
    }
    if (t < nb) g_part[t] = sh[t] - v;  // exclusive
}
__global__ void scan3_kernel(int n) {
    int idx = blockIdx.x * blockDim.x + threadIdx.x;
    if (idx < n) {
        int val = g_rowptr[1 + idx] + g_part[idx / SC_CH];
        g_rowptr[1 + idx] = val;
        if (idx + 1 < n) g_cursor[idx + 1] = val;
    }
    if (idx == 0) { g_rowptr[0] = 0; g_cursor[0] = 0; }
}
__global__ void fillcsr_kernel(const int* __restrict__ src, const int* __restrict__ dst, int e) {
    int i = blockIdx.x * blockDim.x + threadIdx.x;
    if (i < e) {
        int d = dst[i];
        int pos = atomicAdd(&g_cursor[d], 1);
        g_col[pos] = src[i];
    }
}

// ================= tensor-core GEMM (split-fp16, 2-term, mma.sync) ============
// out[n,108] = act( A @ W + bias ); A from fp32 (X1f) or pre-split pairs.
// mode 0: store fp32 + split; mode 1: relu store fp32; mode 2: L2-norm+relu+residual (+split)
__global__ __launch_bounds__(256, 2)
void gemm_tc(const float* __restrict__ X1f,
             const uint32_t* __restrict__ Ah1, const uint32_t* __restrict__ Al1, int K1,
             const uint32_t* __restrict__ Ah2, const uint32_t* __restrict__ Al2, int K2,
             const uint32_t* __restrict__ Wh, int wstride,
             const float* __restrict__ bias,
             float* __restrict__ out, float* __restrict__ hres,
             uint32_t* __restrict__ outH, uint32_t* __restrict__ outL,
             int n, int K, int mode) {
    extern __shared__ char sm[];
    const uint32_t sb = smem_to_u32(sm);
    const int tid = threadIdx.x;
    const int wid = tid >> 5;
    const int lane = tid & 31;
    const int row0 = blockIdx.x * 128;
    float* bias_s = (float*)(sm + SM_BIAS);
    float* inv_s  = (float*)(sm + SM_INV);
    float* Ds     = (float*)(sm + SM_D);

    if (tid < 112) bias_s[tid] = (tid < HH) ? bias[tid] : 0.f;

    float acc[14][4];
#pragma unroll
    for (int nt = 0; nt < 14; nt++)
#pragma unroll
        for (int q = 0; q < 4; q++) acc[nt][q] = 0.f;

    const int warp_r0 = wid * 16;
    const int a_row = warp_r0 + (lane & 15);
    const int a_kb  = (lane >> 4) * 16;
    const int b_row = lane & 7;
    const int b_kb  = ((lane >> 3) & 1) * 16;
    const int K1u = K1 >> 1, K2u = K2 >> 1;

    const int NC = (K + 63) >> 6;
    for (int c = 0; c < NC; c++) {
        const int kc = c << 6;
        __syncthreads();
        // ---- fill A (128 rows x 64 k), swizzled ----
        if (X1f) {
            for (int j = tid; j < 128 * 32; j += 256) {
                int row = j >> 5, kp = j & 31;
                int kk = kc + kp * 2;
                int grow = row0 + row;
                float x0 = 0.f, x1 = 0.f;
                if (grow < n) {
                    if (kk < K) x0 = X1f[grow * K + kk];
                    if (kk + 1 < K) x1 = X1f[grow * K + kk + 1];
                }
                uint32_t hp, lp;
                split2h(x0, x1, hp, lp);
                uint32_t off = SWZ128((uint32_t)(row * 128 + kp * 4));
                *(uint32_t*)(sm + SM_AH + off) = hp;
                *(uint32_t*)(sm + SM_AL + off) = lp;
            }
        } else {
            for (int j = tid; j < 128 * 32; j += 256) {
                int row = j >> 5, kp = j & 31;
                int kk = kc + kp * 2;
                int grow = row0 + row;
                uint32_t hp = 0, lp = 0;
                if (grow < n && kk < K) {
                    if (kk < K1) {
                        int idx = grow * K1u + (kk >> 1);
                        hp = Ah1[idx]; lp = Al1[idx];
                    } else {
                        int idx = grow * K2u + ((kk - K1) >> 1);
                        hp = Ah2[idx]; lp = Al2[idx];
                    }
                }
                uint32_t off = SWZ128((uint32_t)(row * 128 + kp * 4));
                *(uint32_t*)(sm + SM_AH + off) = hp;
                *(uint32_t*)(sm + SM_AL + off) = lp;
            }
        }
        // ---- fill B from prepped weights (112 x 64), swizzled ----
        for (int j = tid; j < 112 * 32; j += 256) {
            int nn = j >> 5, kp = j & 31;
            int idx = nn * wstride + (kc >> 1) + kp;
            uint32_t off = SWZ128((uint32_t)(nn * 128 + kp * 4));
            *(uint32_t*)(sm + SM_BH + off) = Wh[idx];
        }
        __syncthreads();
        // ---- MMA: 4 k-steps x 14 n-tiles x 2 terms ----
#pragma unroll
        for (int ks = 0; ks < 4; ks++) {
            uint32_t aloc = SWZ128((uint32_t)(a_row * 128 + a_kb + ks * 32));
            uint32_t ah[4], al[4];
            ldm_x4(ah, sb + SM_AH + aloc);
            ldm_x4(al, sb + SM_AL + aloc);
            uint32_t bloc = SWZ128((uint32_t)(b_row * 128 + b_kb + ks * 32));
#pragma unroll
            for (int nt = 0; nt < 14; nt++) {
                uint32_t bh[2];
                ldm_x2(bh, sb + SM_BH + bloc + nt * 1024);
                mma_fp16(acc[nt], ah, bh);
                mma_fp16(acc[nt], al, bh);
            }
        }
    }
    __syncthreads();

    // ---- epilogue: accumulators -> smem stage (+bias) ----
    {
        int er = warp_r0 + (lane >> 2);
        int ec = (lane & 3) * 2;
#pragma unroll
        for (int nt = 0; nt < 14; nt++) {
            int col = nt * 8 + ec;
            float b0 = bias_s[col], b1 = bias_s[col + 1];
            float2 lo = make_float2(acc[nt][0] + b0, acc[nt][1] + b1);
            float2 hi = make_float2(acc[nt][2] + b0, acc[nt][3] + b1);
            *(float2*)(Ds + er * D_PITCH + col) = lo;
            *(float2*)(Ds + (er + 8) * D_PITCH + col) = hi;
        }
    }
    __syncwarp();

    if (mode == 2) {
        for (int rr = 0; rr < 16; rr++) {
            int row = warp_r0 + rr;
            const float* dr = Ds + row * D_PITCH;
            float v0 = dr[lane], v1 = dr[lane + 32], v2 = dr[lane + 64];
            float v3 = (lane < 12) ? dr[lane + 96] : 0.f;
            float ss = v0 * v0 + v1 * v1 + v2 * v2 + v3 * v3;
#pragma unroll
            for (int o = 16; o; o >>= 1) ss += __shfl_xor_sync(0xFFFFFFFFu, ss, o);
            if (lane == 0) inv_s[row] = 1.f / fmaxf(sqrtf(ss), 1e-12f);
        }
    }
    __syncthreads();

    // ---- coalesced writeback ----
    for (int i = tid; i < 128 * 27; i += 256) {
        int row = i / 27;
        int v = i - row * 27;
        int grow = row0 + row;
        if (grow >= n) continue;
        float4 d4 = *(const float4*)(Ds + row * D_PITCH + v * 4);
        if (mode == 0) {
            *(float4*)(out + grow * HH + v * 4) = d4;
        } else if (mode == 1) {
            d4.x = fmaxf(d4.x, 0.f); d4.y = fmaxf(d4.y, 0.f);
            d4.z = fmaxf(d4.z, 0.f); d4.w = fmaxf(d4.w, 0.f);
            *(float4*)(out + grow * HH + v * 4) = d4;
        } else {
            float s = inv_s[row];
            float4 h4 = *(const float4*)(hres + grow * HH + v * 4);
            h4.x += fmaxf(d4.x * s, 0.f);
            h4.y += fmaxf(d4.y * s, 0.f);
            h4.z += fmaxf(d4.z * s, 0.f);
            h4.w += fmaxf(d4.w * s, 0.f);
            *(float4*)(hres + grow * HH + v * 4) = h4;
            d4 = h4;
        }
        if ((mode == 0 || mode == 2) && outH) {
            uint32_t hp0, lp0, hp1, lp1;
            split2h(d4.x, d4.y, hp0, lp0);
            split2h(d4.z, d4.w, hp1, lp1);
            outH[grow * HU + v * 2] = hp0;
            outH[grow * HU + v * 2 + 1] = hp1;
            outL[grow * HU + v * 2] = lp0;
            outL[grow * HU + v * 2 + 1] = lp1;
        }
    }
}

// ===== mean aggregation over CSR (warp/node, float4, 4-edge unroll) -> split c
__global__ void aggregate_kernel(const float* __restrict__ z,
                                 uint32_t* __restrict__ ch, uint32_t* __restrict__ cl, int n) {
    int w = (blockIdx.x * blockDim.x + threadIdx.x) >> 5;
    int lane = threadIdx.x & 31;
    if (w >= n || lane >= 27) return;
    int s = g_rowptr[w], e = g_rowptr[w + 1];
    float4 a0 = make_float4(0.f, 0.f, 0.f, 0.f);
    float4 a1 = make_float4(0.f, 0.f, 0.f, 0.f);
    int i = s;
    for (; i + 3 < e; i += 4) {
        int c0 = g_col[i], c1 = g_col[i + 1], c2 = g_col[i + 2], c3 = g_col[i + 3];
        const float4 v0 = ((const float4*)(z + (size_t)c0 * HH))[lane];
        const float4 v1 = ((const float4*)(z + (size_t)c1 * HH))[lane];
        const float4 v2 = ((const float4*)(z + (size_t)c2 * HH))[lane];
        const float4 v3 = ((const float4*)(z + (size_t)c3 * HH))[lane];
        a0.x += v0.x; a0.y += v0.y; a0.z += v0.z; a0.w += v0.w;
        a1.x += v1.x; a1.y += v1.y; a1.z += v1.z; a1.w += v1.w;
        a0.x += v2.x; a0.y += v2.y; a0.z += v2.z; a0.w += v2.w;
        a1.x += v3.x; a1.y += v3.y; a1.z += v3.z; a1.w += v3.w;
    }
    for (; i < e; i++) {
        const float4 v0 = ((const float4*)(z + (size_t)g_col[i] * HH))[lane];
        a0.x += v0.x; a0.y += v0.y; a0.z += v0.z; a0.w += v0.w;
    }
    float inv = 1.f / (float)max(e - s, 1);
    float cx = (a0.x + a1.x) * inv, cy = (a0.y + a1.y) * inv;
    float cz = (a0.z + a1.z) * inv, cw = (a0.w + a1.w) * inv;
    uint32_t hp0, lp0, hp1, lp1;
    split2h(cx, cy, hp0, lp0);
    split2h(cz, cw, hp1, lp1);
    ch[w * HU + lane * 2] = hp0;
    ch[w * HU + lane * 2 + 1] = hp1;
    cl[w * HU + lane * 2] = lp0;
    cl[w * HU + lane * 2 + 1] = lp1;
}

// ================= graph readout =================
__global__ void readout_zero_kernel(int g) {
    int i = blockIdx.x * blockDim.x + threadIdx.x;
    if (i < g * HH) g_hg[i] = 0.f;
    if (i < g) g_cnt[i] = 0.f;
}
__global__ void readout_kernel(const float* __restrict__ h, const int* __restrict__ gids, int n) {
    int w = (blockIdx.x * blockDim.x + threadIdx.x) >> 5;
    int lane = threadIdx.x & 31;
    if (w >= n) return;
    int g = gids[w];
    const float* hr = h + (size_t)w * HH;
    atomicAdd(&g_hg[g * HH + lane], hr[lane]);
    atomicAdd(&g_hg[g * HH + lane + 32], hr[lane + 32]);
    atomicAdd(&g_hg[g * HH + lane + 64], hr[lane + 64]);
    if (lane < 12) atomicAdd(&g_hg[g * HH + lane + 96], hr[lane + 96]);
    if (lane == 0) atomicAdd(&g_cnt[g], 1.f);
}
__global__ void finalize_kernel(float* __restrict__ out, int total) {
    int i = blockIdx.x * blockDim.x + threadIdx.x;
    if (i < total) out[i] = g_hg[i] / fmaxf(g_cnt[i / HH], 1.f);
}

// ================= launch =================
extern "C" void kernel_launch(void* const* d_in, const int* in_sizes, int n_in,
                              void* d_out, int out_size) {
    const float* nodes_feat = (const float*)d_in[0];
    const float* W_emb  = (const float*)d_in[4];
    const float* b_emb  = (const float*)d_in[5];
    const float* pool_W = (const float*)d_in[6];
    const float* pool_b = (const float*)d_in[7];
    const float* app_W  = (const float*)d_in[8];
    const float* app_b  = (const float*)d_in[9];
    const int* src  = (const int*)d_in[10];
    const int* dst  = (const int*)d_in[11];
    const int* gids = (const int*)d_in[12];

    const int n = in_sizes[12];
    const int e = in_sizes[10];
    const int in_dim = in_sizes[4] / HH;
    const int n_layers = in_sizes[6] / (HH * HH);
    const int G = out_size / HH;

    float *hP, *zP;
    uint32_t *hhP, *hlP, *chP, *clP, *whP;
    cudaGetSymbolAddress((void**)&hP, g_h);
    cudaGetSymbolAddress((void**)&zP, g_z);
    cudaGetSymbolAddress((void**)&hhP, g_hh);
    cudaGetSymbolAddress((void**)&hlP, g_hl);
    cudaGetSymbolAddress((void**)&chP, g_ch);
    cudaGetSymbolAddress((void**)&clP, g_cl);
    cudaGetSymbolAddress((void**)&whP, g_wh);

    cudaFuncSetAttribute(gemm_tc, cudaFuncAttributeMaxDynamicSharedMemorySize, SM_TOTAL);

    // weight layout (u32 units)
    const int KPe = ((in_dim + 63) / 64) * 64;
    const int u_emb = 112 * (KPe >> 1);
    const int u_pool = 112 * 64;
    const int u_app = 112 * 128;
    const int w_total = u_emb + n_layers * (u_pool + u_app);

    const int gB = (n + 127) / 128;
    int warp_blocks = ((n * 32) + 255) / 256;

    // launch order arranged so the 4th launch (ncu capture slot) is gemm_tc(emb)
    zero_deg_kernel<<<(n + 255) / 256, 256>>>(n);                                     // 1
    hist_kernel<<<(e + 255) / 256, 256>>>(dst, e);                                    // 2
    prep_w<<<(w_total + 255) / 256, 256>>>(W_emb, in_dim, KPe, pool_W, app_W,
                                           n_layers, w_total);                        // 3
    // ---- embedding: h = nodes_feat @ W_emb + b_emb (fp32 A path) ----
    gemm_tc<<<gB, 256, SM_TOTAL>>>(nodes_feat,                                        // 4
                                   (const uint32_t*)0, (const uint32_t*)0, in_dim,
                                   (const uint32_t*)0, (const uint32_t*)0, 0,
                                   whP, KPe >> 1,
                                   b_emb, hP, (float*)0, hhP, hlP, n, in_dim, 0);
    // ---- CSR by dst ----
    int nb = (n + SC_CH - 1) / SC_CH;
    scan1_kernel<<<nb, SC_T>>>(n);                                                    // 5
    scan2_kernel<<<1, 256>>>(nb);                                                     // 6
    scan3_kernel<<<(n + 255) / 256, 256>>>(n);                                        // 7
    fillcsr_kernel<<<(e + 255) / 256, 256>>>(src, dst, e);                            // 8

    for (int l = 0; l < n_layers; l++) {
        const float* pb = pool_b + (size_t)l * HH;
        const float* ab = app_b + (size_t)l * HH;
        const uint32_t* pWh = whP + u_emb + l * u_pool;
        const uint32_t* aWh = whP + u_emb + n_layers * u_pool + l * u_app;

        // z = relu(h @ pool_W + pool_b)
        gemm_tc<<<gB, 256, SM_TOTAL>>>((const float*)0,
                                       hhP, hlP, HH,
                                       (const uint32_t*)0, (const uint32_t*)0, 0,
                                       pWh, 64,
                                       pb, zP, (float*)0, (uint32_t*)0, (uint32_t*)0,
                                       n, HH, 1);
        // c = mean_{u in N(v)} z[u]  (written pre-split)
        aggregate_kernel<<<warp_blocks, 256>>>(zP, chP, clP, n);
        // h += relu(l2norm([h|c] @ app_W + app_b)); split-write h unless last layer
        int last = (l == n_layers - 1);
        gemm_tc<<<gB, 256, SM_TOTAL>>>((const float*)0,
                                       hhP, hlP, HH,
                                       chP, clP, HH,
                                       aWh, 128,
                                       ab, (float*)0, hP,
                                       last ? (uint32_t*)0 : hhP,
                                       last ? (uint32_t*)0 : hlP,
                                       n, 2 * HH, 2);
    }

    // ---- readout: per-graph mean ----
    readout_zero_kernel<<<(G * HH + 255) / 256, 256>>>(G);
    readout_kernel<<<warp_blocks, 256>>>(hP, gids, n);
    finalize_kernel<<<(out_size + 255) / 256, 256>>>((float*)d_out, out_size);
}

// round 6
// speedup vs baseline: 2.2959x; 1.4325x over previous
#include <cuda_runtime.h>
#include <cuda_fp16.h>
#include <math.h>
#include <stdint.h>

#define HH 108
#define HP 64               // padded u32 pitch for split rows (256B)
#define NCAP 100000
#define ECAP 1600000
#define GCAP 1024
#define SC_T 256
#define SC_I 8
#define SC_CH (SC_T * SC_I)

// -------- device scratch --------
__device__ float    g_h[NCAP * HH];
__device__ float    g_z[NCAP * HH];
__device__ uint32_t g_hh[NCAP * HP];
__device__ uint32_t g_hl[NCAP * HP];
__device__ uint32_t g_ch[NCAP * HP];
__device__ uint32_t g_cl[NCAP * HP];
__device__ uint32_t g_wh[65536];
__device__ int   g_deg[NCAP];
__device__ int   g_rowptr[NCAP + 1];
__device__ int   g_cursor[NCAP];
__device__ int   g_col[ECAP];
__device__ int   g_part[256];
__device__ float g_hg[GCAP * HH];
__device__ float g_cnt[GCAP];

// ================= helpers =================
__device__ __forceinline__ uint32_t smem_to_u32(const void* smem_ptr) {
    uint32_t addr;
    asm("{ .reg .u64 tmp; cvta.to.shared.u64 tmp, %1; cvt.u32.u64 %0, tmp; }"
        : "=r"(addr) : "l"(smem_ptr));
    return addr;
}
__device__ __forceinline__ void ldm_x4(uint32_t* r, uint32_t addr) {
    asm volatile("ldmatrix.sync.aligned.m8n8.x4.shared.b16 {%0,%1,%2,%3}, [%4];"
        : "=r"(r[0]), "=r"(r[1]), "=r"(r[2]), "=r"(r[3]) : "r"(addr));
}
__device__ __forceinline__ void ldm_x2(uint32_t* r, uint32_t addr) {
    asm volatile("ldmatrix.sync.aligned.m8n8.x2.shared.b16 {%0,%1}, [%2];"
        : "=r"(r[0]), "=r"(r[1]) : "r"(addr));
}
__device__ __forceinline__ void mma_fp16(float* c, const uint32_t* a, const uint32_t* b) {
    asm volatile(
        "mma.sync.aligned.m16n8k16.row.col.f32.f16.f16.f32 "
        "{%0,%1,%2,%3}, {%4,%5,%6,%7}, {%8,%9}, {%0,%1,%2,%3};"
        : "+f"(c[0]), "+f"(c[1]), "+f"(c[2]), "+f"(c[3])
        : "r"(a[0]), "r"(a[1]), "r"(a[2]), "r"(a[3]), "r"(b[0]), "r"(b[1]));
}
__device__ __forceinline__ void cp16(uint32_t dst, const void* src, int sz) {
    asm volatile("cp.async.cg.shared.global [%0], [%1], 16, %2;"
                 :: "r"(dst), "l"(src), "r"(sz) : "memory");
}
#define CP_COMMIT() asm volatile("cp.async.commit_group;" ::: "memory")
#define CP_WAIT1()  asm volatile("cp.async.wait_group 1;" ::: "memory")
#define SWZ128(b) ((b) ^ (((b) >> 3) & 0x70))

__device__ __forceinline__ void split2h(float x, float y, uint32_t& hp, uint32_t& lp) {
    __half hx = __float2half_rn(x), hy = __float2half_rn(y);
    float lx = x - __half2float(hx), ly = y - __half2float(hy);
    hp = ((uint32_t)__half_as_ushort(hy) << 16) | __half_as_ushort(hx);
    lp = ((uint32_t)__half_as_ushort(__float2half_rn(ly)) << 16)
       | __half_as_ushort(__float2half_rn(lx));
}
__device__ __forceinline__ uint32_t pack_h(float x, float y) {
    return ((uint32_t)__half_as_ushort(__float2half_rn(y)) << 16)
         | __half_as_ushort(__float2half_rn(x));
}

// ================= smem layout: double-buffered stages =================
#define SM_BIAS 0        // 112 floats
#define SM_AH   1024
#define SM_AL   (SM_AH + 16384)
#define SM_BH   (SM_AL + 16384)
#define STG     47104    // stage stride (AH+AL+BH = 16384+16384+14336)
#define SM_TOTAL (1024 + 2 * STG)   // 95232

// ================= weight prep =================
// layout (u32): emb [112 x KPe/2] | pool_l [112 x 64] | app_l [112 x 128]
// app logical K = 256: k<128 -> W[k] (k<108), k>=128 -> W[108 + (k-128)] (<108)
__global__ void prep_w(const float* __restrict__ W_emb, int Kemb, int KPe,
                       const float* __restrict__ pool_W,
                       const float* __restrict__ app_W, int n_layers, int total) {
    int idx = blockIdx.x * blockDim.x + threadIdx.x;
    if (idx >= total) return;
    const float* Wp = 0;
    int K = 0, KP = 0, rel = idx, off = 0, is_app = 0;
    int sz = 112 * (KPe >> 1);
    if (idx < sz) { Wp = W_emb; K = Kemb; KP = KPe; rel = idx; }
    else {
        off = sz;
        for (int l = 0; l < n_layers && !Wp; l++) {
            if (idx < off + 112 * 64) { Wp = pool_W + l * HH * HH; K = HH; KP = 128; rel = idx - off; }
            off += 112 * 64;
        }
        for (int l = 0; l < n_layers && !Wp; l++) {
            if (idx < off + 112 * 128) { Wp = app_W + l * 2 * HH * HH; K = 2 * HH; KP = 256; rel = idx - off; is_app = 1; }
            off += 112 * 128;
        }
        if (!Wp) return;
    }
    int nn = rel / (KP >> 1);
    int kp = rel - nn * (KP >> 1);
    float w[2];
#pragma unroll
    for (int q = 0; q < 2; q++) {
        int k = kp * 2 + q;
        int kk, valid;
        if (is_app) {
            if (k < 128) { kk = k; valid = (k < HH); }
            else { kk = HH + (k - 128); valid = (k - 128 < HH); }
        } else { kk = k; valid = (k < K); }
        w[q] = (nn < HH && valid) ? Wp[kk * HH + nn] : 0.f;
    }
    g_wh[idx] = pack_h(w[0], w[1]);
}

// ================= CSR build =================
__global__ void zero_deg_kernel(int n) {
    int i = blockIdx.x * blockDim.x + threadIdx.x;
    if (i < n) g_deg[i] = 0;
}
__global__ void hist_kernel(const int* __restrict__ dst, int e) {
    int i = blockIdx.x * blockDim.x + threadIdx.x;
    if (i < e) atomicAdd(&g_deg[dst[i]], 1);
}
__global__ void scan1_kernel(int n) {
    __shared__ int sh[SC_T];
    int t = threadIdx.x, b = blockIdx.x;
    int base = b * SC_CH + t * SC_I;
    int v[SC_I];
    int run = 0;
#pragma unroll
    for (int j = 0; j < SC_I; j++) {
        int idx = base + j;
        int x = (idx < n) ? g_deg[idx] : 0;
        run += x;
        v[j] = run;
    }
    sh[t] = run;
    __syncthreads();
    for (int off = 1; off < SC_T; off <<= 1) {
        int x = (t >= off) ? sh[t - off] : 0;
        __syncthreads();
        sh[t] += x;
        __syncthreads();
    }
    int excl = sh[t] - run;
#pragma unroll
    for (int j = 0; j < SC_I; j++) {
        int idx = base + j;
        if (idx < n) g_rowptr[1 + idx] = excl + v[j];
    }
    if (t == SC_T - 1) g_part[b] = sh[t];
}
__global__ void scan2_kernel(int nb) {
    __shared__ int sh[256];
    int t = threadIdx.x;
    int v = (t < nb) ? g_part[t] : 0;
    sh[t] = v;
    __syncthreads();
    for (int off = 1; off < 256; off <<= 1) {
        int x = (t >= off) ? sh[t - off] : 0;
        __syncthreads();
        sh[t] += x;
        __syncthreads();
    }
    if (t < nb) g_part[t] = sh[t] - v;
}
__global__ void scan3_kernel(int n) {
    int idx = blockIdx.x * blockDim.x + threadIdx.x;
    if (idx < n) {
        int val = g_rowptr[1 + idx] + g_part[idx / SC_CH];
        g_rowptr[1 + idx] = val;
        if (idx + 1 < n) g_cursor[idx + 1] = val;
    }
    if (idx == 0) { g_rowptr[0] = 0; g_cursor[0] = 0; }
}
__global__ void fillcsr_kernel(const int* __restrict__ src, const int* __restrict__ dst, int e) {
    int i = blockIdx.x * blockDim.x + threadIdx.x;
    if (i < e) {
        int d = dst[i];
        int pos = atomicAdd(&g_cursor[d], 1);
        g_col[pos] = src[i];
    }
}

// ================= tensor-core GEMM (split-fp16, 2-term, cp.async pipeline) ===
// mode 0: store fp32 (+ split); mode 1: relu store fp32; mode 2: L2-norm+relu+residual (+split)
__global__ __launch_bounds__(256, 2)
void gemm_tc(const float* __restrict__ X1f,
             const uint32_t* __restrict__ Ah1, const uint32_t* __restrict__ Al1,
             const uint32_t* __restrict__ Ah2, const uint32_t* __restrict__ Al2,
             const uint32_t* __restrict__ Wh, int wstride,
             const float* __restrict__ bias,
             float* __restrict__ out, float* __restrict__ hres,
             uint32_t* __restrict__ outH, uint32_t* __restrict__ outL,
             int n, int K, int NC1, int mode) {
    extern __shared__ char sm[];
    const uint32_t sb = smem_to_u32(sm);
    const int tid = threadIdx.x;
    const int wid = tid >> 5;
    const int lane = tid & 31;
    const int row0 = blockIdx.x * 128;
    float* bias_s = (float*)(sm + SM_BIAS);

    if (tid < 112) bias_s[tid] = (tid < HH) ? bias[tid] : 0.f;

    float acc[14][4];
#pragma unroll
    for (int nt = 0; nt < 14; nt++)
#pragma unroll
        for (int q = 0; q < 4; q++) acc[nt][q] = 0.f;

    const int warp_r0 = wid * 16;
    const int a_row = warp_r0 + (lane & 15);
    const int a_kb  = (lane >> 4) * 16;
    const int b_row = lane & 7;
    const int b_kb  = ((lane >> 3) & 1) * 16;
    const int NC = K >> 6;

    // async fill of chunk c into stage s (split-A path)
    auto issue_fill = [&](int c, int s) {
        const uint32_t* srcH = (c < NC1) ? Ah1 : Ah2;
        const uint32_t* srcL = (c < NC1) ? Al1 : Al2;
        int coff = ((c < NC1) ? c : (c - NC1)) * 32;
        uint32_t base = sb + s * STG;
        for (int idx = tid; idx < 2048; idx += 256) {
            int u = idx & 7;
            int row = (idx >> 3) & 127;
            int hi = idx < 1024;
            int grow = row0 + row;
            const uint32_t* src = (hi ? srcH : srcL) + (size_t)grow * HP + coff + u * 4;
            uint32_t dst = base + (hi ? SM_AH : SM_AL) + SWZ128((uint32_t)(row * 128 + u * 16));
            cp16(dst, src, grow < n ? 16 : 0);
        }
        int kc32 = c * 32;
        for (int idx = tid; idx < 896; idx += 256) {
            int u = idx & 7;
            int nn = idx >> 3;
            const uint32_t* src = Wh + nn * wstride + kc32 + u * 4;
            uint32_t dst = base + SM_BH + SWZ128((uint32_t)(nn * 128 + u * 16));
            cp16(dst, src, 16);
        }
    };

    if (X1f) {
        // synchronous fp32 path (emb; NC small)
        for (int c = 0; c < NC; c++) {
            const int kc = c << 6;
            __syncthreads();
            for (int j = tid; j < 128 * 32; j += 256) {
                int row = j >> 5, kp = j & 31;
                int kk = kc + kp * 2;
                int grow = row0 + row;
                float x0 = 0.f, x1 = 0.f;
                if (grow < n) {
                    if (kk < K) x0 = X1f[grow * K + kk];
                    if (kk + 1 < K) x1 = X1f[grow * K + kk + 1];
                }
                uint32_t hp, lp;
                split2h(x0, x1, hp, lp);
                uint32_t off = SWZ128((uint32_t)(row * 128 + kp * 4));
                *(uint32_t*)(sm + SM_AH + off) = hp;
                *(uint32_t*)(sm + SM_AL + off) = lp;
            }
            for (int j = tid; j < 112 * 32; j += 256) {
                int nn = j >> 5, kp = j & 31;
                *(uint32_t*)(sm + SM_BH + SWZ128((uint32_t)(nn * 128 + kp * 4)))
                    = Wh[nn * wstride + (kc >> 1) + kp];
            }
            __syncthreads();
#pragma unroll
            for (int ks = 0; ks < 4; ks++) {
                uint32_t aloc = SWZ128((uint32_t)(a_row * 128 + a_kb + ks * 32));
                uint32_t ah[4], al[4];
                ldm_x4(ah, sb + SM_AH + aloc);
                ldm_x4(al, sb + SM_AL + aloc);
                uint32_t bloc = SWZ128((uint32_t)(b_row * 128 + b_kb + ks * 32));
#pragma unroll
                for (int nt = 0; nt < 14; nt++) {
                    uint32_t bh[2];
                    ldm_x2(bh, sb + SM_BH + bloc + nt * 1024);
                    mma_fp16(acc[nt], ah, bh);
                    mma_fp16(acc[nt], al, bh);
                }
            }
        }
    } else {
        // pipelined split path
        issue_fill(0, 0);
        CP_COMMIT();
        for (int c = 0; c < NC; c++) {
            int s = c & 1;
            if (c + 1 < NC) issue_fill(c + 1, s ^ 1);
            CP_COMMIT();
            CP_WAIT1();
            __syncthreads();
            uint32_t base = sb + s * STG;
#pragma unroll
            for (int ks = 0; ks < 4; ks++) {
                uint32_t aloc = SWZ128((uint32_t)(a_row * 128 + a_kb + ks * 32));
                uint32_t ah[4], al[4];
                ldm_x4(ah, base + SM_AH + aloc);
                ldm_x4(al, base + SM_AL + aloc);
                uint32_t bloc = SWZ128((uint32_t)(b_row * 128 + b_kb + ks * 32));
#pragma unroll
                for (int nt = 0; nt < 14; nt++) {
                    uint32_t bh[2];
                    ldm_x2(bh, base + SM_BH + bloc + nt * 1024);
                    mma_fp16(acc[nt], ah, bh);
                    mma_fp16(acc[nt], al, bh);
                }
            }
            if (c + 2 < NC) __syncthreads();  // stage s reused by prefetch next iter
        }
    }

    // ---- direct register epilogue ----
    const int er = warp_r0 + (lane >> 2);
    const int ec = (lane & 3) * 2;
    const int glo = row0 + er, ghi = glo + 8;
    float ss0 = 0.f, ss1 = 0.f;
#pragma unroll
    for (int nt = 0; nt < 14; nt++) {
        int col = nt * 8 + ec;
        float b0 = bias_s[col], b1 = bias_s[col + 1];
        acc[nt][0] += b0; acc[nt][1] += b1;
        acc[nt][2] += b0; acc[nt][3] += b1;
        if (mode == 2) {
            ss0 += acc[nt][0] * acc[nt][0] + acc[nt][1] * acc[nt][1];
            ss1 += acc[nt][2] * acc[nt][2] + acc[nt][3] * acc[nt][3];
        }
    }
    float s0 = 1.f, s1 = 1.f;
    if (mode == 2) {
        ss0 += __shfl_xor_sync(0xFFFFFFFFu, ss0, 1);
        ss0 += __shfl_xor_sync(0xFFFFFFFFu, ss0, 2);
        ss1 += __shfl_xor_sync(0xFFFFFFFFu, ss1, 1);
        ss1 += __shfl_xor_sync(0xFFFFFFFFu, ss1, 2);
        s0 = 1.f / fmaxf(sqrtf(ss0), 1e-12f);
        s1 = 1.f / fmaxf(sqrtf(ss1), 1e-12f);
    }
#pragma unroll
    for (int nt = 0; nt < 14; nt++) {
        int col = nt * 8 + ec;
        if (col >= HH) continue;
        float v0 = acc[nt][0], v1 = acc[nt][1], v2 = acc[nt][2], v3 = acc[nt][3];
        if (mode == 1) {
            v0 = fmaxf(v0, 0.f); v1 = fmaxf(v1, 0.f);
            v2 = fmaxf(v2, 0.f); v3 = fmaxf(v3, 0.f);
        }
        if (mode == 2) {
            if (glo < n) {
                float2 h0 = *(const float2*)(hres + (size_t)glo * HH + col);
                v0 = h0.x + fmaxf(v0 * s0, 0.f);
                v1 = h0.y + fmaxf(v1 * s0, 0.f);
            }
            if (ghi < n) {
                float2 h1 = *(const float2*)(hres + (size_t)ghi * HH + col);
                v2 = h1.x + fmaxf(v2 * s1, 0.f);
                v3 = h1.y + fmaxf(v3 * s1, 0.f);
            }
        }
        float* o_lo = (mode == 2) ? hres : out;
        if (glo < n) *(float2*)(o_lo + (size_t)glo * HH + col) = make_float2(v0, v1);
        if (ghi < n) *(float2*)(o_lo + (size_t)ghi * HH + col) = make_float2(v2, v3);
        if (outH) {
            uint32_t hp, lp;
            if (glo < n) {
                split2h(v0, v1, hp, lp);
                outH[(size_t)glo * HP + (col >> 1)] = hp;
                outL[(size_t)glo * HP + (col >> 1)] = lp;
            }
            if (ghi < n) {
                split2h(v2, v3, hp, lp);
                outH[(size_t)ghi * HP + (col >> 1)] = hp;
                outL[(size_t)ghi * HP + (col >> 1)] = lp;
            }
        }
    }
}

// ===== mean aggregation over CSR (warp/node, float4, 4-edge unroll) -> split c
__global__ void aggregate_kernel(const float* __restrict__ z,
                                 uint32_t* __restrict__ ch, uint32_t* __restrict__ cl, int n) {
    int w = (blockIdx.x * blockDim.x + threadIdx.x) >> 5;
    int lane = threadIdx.x & 31;
    if (w >= n || lane >= 27) return;
    int s = g_rowptr[w], e = g_rowptr[w + 1];
    float4 a0 = make_float4(0.f, 0.f, 0.f, 0.f);
    float4 a1 = make_float4(0.f, 0.f, 0.f, 0.f);
    int i = s;
    for (; i + 3 < e; i += 4) {
        int c0 = g_col[i], c1 = g_col[i + 1], c2 = g_col[i + 2], c3 = g_col[i + 3];
        const float4 v0 = ((const float4*)(z + (size_t)c0 * HH))[lane];
        const float4 v1 = ((const float4*)(z + (size_t)c1 * HH))[lane];
        const float4 v2 = ((const float4*)(z + (size_t)c2 * HH))[lane];
        const float4 v3 = ((const float4*)(z + (size_t)c3 * HH))[lane];
        a0.x += v0.x; a0.y += v0.y; a0.z += v0.z; a0.w += v0.w;
        a1.x += v1.x; a1.y += v1.y; a1.z += v1.z; a1.w += v1.w;
        a0.x += v2.x; a0.y += v2.y; a0.z += v2.z; a0.w += v2.w;
        a1.x += v3.x; a1.y += v3.y; a1.z += v3.z; a1.w += v3.w;
    }
    for (; i < e; i++) {
        const float4 v0 = ((const float4*)(z + (size_t)g_col[i] * HH))[lane];
        a0.x += v0.x; a0.y += v0.y; a0.z += v0.z; a0.w += v0.w;
    }
    float inv = 1.f / (float)max(e - s, 1);
    float cx = (a0.x + a1.x) * inv, cy = (a0.y + a1.y) * inv;
    float cz = (a0.z + a1.z) * inv, cw = (a0.w + a1.w) * inv;
    uint32_t hp0, lp0, hp1, lp1;
    split2h(cx, cy, hp0, lp0);
    split2h(cz, cw, hp1, lp1);
    ch[w * HP + lane * 2] = hp0;
    ch[w * HP + lane * 2 + 1] = hp1;
    cl[w * HP + lane * 2] = lp0;
    cl[w * HP + lane * 2 + 1] = lp1;
}

// ================= graph readout =================
__global__ void readout_zero_kernel(int g) {
    int i = blockIdx.x * blockDim.x + threadIdx.x;
    if (i < g * HH) g_hg[i] = 0.f;
    if (i < g) g_cnt[i] = 0.f;
}
__global__ void readout_kernel(const float* __restrict__ h, const int* __restrict__ gids, int n) {
    int w = (blockIdx.x * blockDim.x + threadIdx.x) >> 5;
    int lane = threadIdx.x & 31;
    if (w >= n) return;
    int g = gids[w];
    const float* hr = h + (size_t)w * HH;
    atomicAdd(&g_hg[g * HH + lane], hr[lane]);
    atomicAdd(&g_hg[g * HH + lane + 32], hr[lane + 32]);
    atomicAdd(&g_hg[g * HH + lane + 64], hr[lane + 64]);
    if (lane < 12) atomicAdd(&g_hg[g * HH + lane + 96], hr[lane + 96]);
    if (lane == 0) atomicAdd(&g_cnt[g], 1.f);
}
__global__ void finalize_kernel(float* __restrict__ out, int total) {
    int i = blockIdx.x * blockDim.x + threadIdx.x;
    if (i < total) out[i] = g_hg[i] / fmaxf(g_cnt[i / HH], 1.f);
}

// ================= launch =================
extern "C" void kernel_launch(void* const* d_in, const int* in_sizes, int n_in,
                              void* d_out, int out_size) {
    const float* nodes_feat = (const float*)d_in[0];
    const float* W_emb  = (const float*)d_in[4];
    const float* b_emb  = (const float*)d_in[5];
    const float* pool_W = (const float*)d_in[6];
    const float* pool_b = (const float*)d_in[7];
    const float* app_W  = (const float*)d_in[8];
    const float* app_b  = (const float*)d_in[9];
    const int* src  = (const int*)d_in[10];
    const int* dst  = (const int*)d_in[11];
    const int* gids = (const int*)d_in[12];

    const int n = in_sizes[12];
    const int e = in_sizes[10];
    const int in_dim = in_sizes[4] / HH;
    const int n_layers = in_sizes[6] / (HH * HH);
    const int G = out_size / HH;

    float *hP, *zP;
    uint32_t *hhP, *hlP, *chP, *clP, *whP;
    cudaGetSymbolAddress((void**)&hP, g_h);
    cudaGetSymbolAddress((void**)&zP, g_z);
    cudaGetSymbolAddress((void**)&hhP, g_hh);
    cudaGetSymbolAddress((void**)&hlP, g_hl);
    cudaGetSymbolAddress((void**)&chP, g_ch);
    cudaGetSymbolAddress((void**)&clP, g_cl);
    cudaGetSymbolAddress((void**)&whP, g_wh);

    cudaFuncSetAttribute(gemm_tc, cudaFuncAttributeMaxDynamicSharedMemorySize, SM_TOTAL);

    const int KPe = ((in_dim + 63) / 64) * 64;
    const int u_emb = 112 * (KPe >> 1);
    const int u_pool = 112 * 64;
    const int u_app = 112 * 128;
    const int w_total = u_emb + n_layers * (u_pool + u_app);

    const int gB = (n + 127) / 128;
    int warp_blocks = ((n * 32) + 255) / 256;

    zero_deg_kernel<<<(n + 255) / 256, 256>>>(n);                                     // 1
    hist_kernel<<<(e + 255) / 256, 256>>>(dst, e);                                    // 2
    prep_w<<<(w_total + 255) / 256, 256>>>(W_emb, in_dim, KPe, pool_W, app_W,
                                           n_layers, w_total);                        // 3
    // ---- embedding (fp32 A path), ncu capture slot #4 ----
    gemm_tc<<<gB, 256, SM_TOTAL>>>(nodes_feat,
                                   (const uint32_t*)0, (const uint32_t*)0,
                                   (const uint32_t*)0, (const uint32_t*)0,
                                   whP, KPe >> 1,
                                   b_emb, hP, (float*)0, hhP, hlP,
                                   n, KPe, 1, 0);
    // ---- CSR by dst ----
    int nb = (n + SC_CH - 1) / SC_CH;
    scan1_kernel<<<nb, SC_T>>>(n);
    scan2_kernel<<<1, 256>>>(nb);
    scan3_kernel<<<(n + 255) / 256, 256>>>(n);
    fillcsr_kernel<<<(e + 255) / 256, 256>>>(src, dst, e);

    for (int l = 0; l < n_layers; l++) {
        const float* pb = pool_b + (size_t)l * HH;
        const float* ab = app_b + (size_t)l * HH;
        const uint32_t* pWh = whP + u_emb + l * u_pool;
        const uint32_t* aWh = whP + u_emb + n_layers * u_pool + l * u_app;

        // z = relu(h @ pool_W + pool_b)   (K padded to 128, 2 chunks)
        gemm_tc<<<gB, 256, SM_TOTAL>>>((const float*)0,
                                       hhP, hlP, (const uint32_t*)0, (const uint32_t*)0,
                                       pWh, 64,
                                       pb, zP, (float*)0, (uint32_t*)0, (uint32_t*)0,
                                       n, 128, 2, 1);
        // c = mean_{u in N(v)} z[u]
        aggregate_kernel<<<warp_blocks, 256>>>(zP, chP, clP, n);
        // h += relu(l2norm([h|c] @ app_W + app_b))   (K padded to 256, 4 chunks)
        int last = (l == n_layers - 1);
        gemm_tc<<<gB, 256, SM_TOTAL>>>((const float*)0,
                                       hhP, hlP, chP, clP,
                                       aWh, 128,
                                       ab, (float*)0, hP,
                                       last ? (uint32_t*)0 : hhP,
                                       last ? (uint32_t*)0 : hlP,
                                       n, 256, 2, 2);
    }

    // ---- readout ----
    readout_zero_kernel<<<(G * HH + 255) / 256, 256>>>(G);
    readout_kernel<<<warp_blocks, 256>>>(hP, gids, n);
    finalize_kernel<<<(out_size + 255) / 256, 256>>>((float*)d_out, out_size);
}

// round 7
// speedup vs baseline: 2.3126x; 1.0073x over previous
#include <cuda_runtime.h>
#include <cuda_fp16.h>
#include <math.h>
#include <stdint.h>

#define HH 108
#define HP 64               // padded u32 pitch for split rows (256B)
#define NCAP 100000
#define ECAP 1600000
#define GCAP 1024
#define SC_T 256
#define SC_I 8
#define SC_CH (SC_T * SC_I)

// -------- device scratch --------
__device__ float    g_h[NCAP * HH];
__device__ float    g_z[NCAP * HH];
__device__ uint32_t g_hh[NCAP * HP];
__device__ uint32_t g_hl[NCAP * HP];
__device__ uint32_t g_ch[NCAP * HP];
__device__ uint32_t g_cl[NCAP * HP];
__device__ uint32_t g_wh[65536];
__device__ int   g_deg[NCAP];
__device__ int   g_rowptr[NCAP + 1];
__device__ int   g_cursor[NCAP];
__device__ int   g_col[ECAP];
__device__ int   g_part[256];
__device__ float g_hg[GCAP * HH];
__device__ float g_cnt[GCAP];

// ================= helpers =================
__device__ __forceinline__ uint32_t smem_to_u32(const void* smem_ptr) {
    uint32_t addr;
    asm("{ .reg .u64 tmp; cvta.to.shared.u64 tmp, %1; cvt.u32.u64 %0, tmp; }"
        : "=r"(addr) : "l"(smem_ptr));
    return addr;
}
__device__ __forceinline__ void ldm_x4(uint32_t* r, uint32_t addr) {
    asm volatile("ldmatrix.sync.aligned.m8n8.x4.shared.b16 {%0,%1,%2,%3}, [%4];"
        : "=r"(r[0]), "=r"(r[1]), "=r"(r[2]), "=r"(r[3]) : "r"(addr));
}
__device__ __forceinline__ void ldm_x2(uint32_t* r, uint32_t addr) {
    asm volatile("ldmatrix.sync.aligned.m8n8.x2.shared.b16 {%0,%1}, [%2];"
        : "=r"(r[0]), "=r"(r[1]) : "r"(addr));
}
__device__ __forceinline__ void mma_fp16(float* c, const uint32_t* a, const uint32_t* b) {
    asm volatile(
        "mma.sync.aligned.m16n8k16.row.col.f32.f16.f16.f32 "
        "{%0,%1,%2,%3}, {%4,%5,%6,%7}, {%8,%9}, {%0,%1,%2,%3};"
        : "+f"(c[0]), "+f"(c[1]), "+f"(c[2]), "+f"(c[3])
        : "r"(a[0]), "r"(a[1]), "r"(a[2]), "r"(a[3]), "r"(b[0]), "r"(b[1]));
}
__device__ __forceinline__ void cp16(uint32_t dst, const void* src, int sz) {
    asm volatile("cp.async.cg.shared.global [%0], [%1], 16, %2;"
                 :: "r"(dst), "l"(src), "r"(sz) : "memory");
}
#define CP_COMMIT() asm volatile("cp.async.commit_group;" ::: "memory")
#define CP_WAIT1()  asm volatile("cp.async.wait_group 1;" ::: "memory")
#define SWZ128(b) ((b) ^ (((b) >> 3) & 0x70))

__device__ __forceinline__ void split2h(float x, float y, uint32_t& hp, uint32_t& lp) {
    __half hx = __float2half_rn(x), hy = __float2half_rn(y);
    float lx = x - __half2float(hx), ly = y - __half2float(hy);
    hp = ((uint32_t)__half_as_ushort(hy) << 16) | __half_as_ushort(hx);
    lp = ((uint32_t)__half_as_ushort(__float2half_rn(ly)) << 16)
       | __half_as_ushort(__float2half_rn(lx));
}
__device__ __forceinline__ uint32_t pack_h(float x, float y) {
    return ((uint32_t)__half_as_ushort(__float2half_rn(y)) << 16)
         | __half_as_ushort(__float2half_rn(x));
}

// ================= smem layout: double-buffered stages =================
#define SM_BIAS 0        // 112 floats
#define SM_AH   1024
#define SM_AL   (SM_AH + 16384)
#define SM_BH   (SM_AL + 16384)
#define STG     47104    // stage stride (AH+AL+BH = 16384+16384+14336)
#define SM_TOTAL (1024 + 2 * STG)   // 95232

// ================= weight prep =================
// layout (u32): emb [112 x KPe/2] | pool_l [112 x 64] | app_l [112 x 128]
// app logical K = 256: k<128 -> W[k] (k<108), k>=128 -> W[108 + (k-128)] (<108)
__global__ void prep_w(const float* __restrict__ W_emb, int Kemb, int KPe,
                       const float* __restrict__ pool_W,
                       const float* __restrict__ app_W, int n_layers, int total) {
    int idx = blockIdx.x * blockDim.x + threadIdx.x;
    if (idx >= total) return;
    const float* Wp = 0;
    int K = 0, KP = 0, rel = idx, off = 0, is_app = 0;
    int sz = 112 * (KPe >> 1);
    if (idx < sz) { Wp = W_emb; K = Kemb; KP = KPe; rel = idx; }
    else {
        off = sz;
        for (int l = 0; l < n_layers && !Wp; l++) {
            if (idx < off + 112 * 64) { Wp = pool_W + l * HH * HH; K = HH; KP = 128; rel = idx - off; }
            off += 112 * 64;
        }
        for (int l = 0; l < n_layers && !Wp; l++) {
            if (idx < off + 112 * 128) { Wp = app_W + l * 2 * HH * HH; K = 2 * HH; KP = 256; rel = idx - off; is_app = 1; }
            off += 112 * 128;
        }
        if (!Wp) return;
    }
    int nn = rel / (KP >> 1);
    int kp = rel - nn * (KP >> 1);
    float w[2];
#pragma unroll
    for (int q = 0; q < 2; q++) {
        int k = kp * 2 + q;
        int kk, valid;
        if (is_app) {
            if (k < 128) { kk = k; valid = (k < HH); }
            else { kk = HH + (k - 128); valid = (k - 128 < HH); }
        } else { kk = k; valid = (k < K); }
        w[q] = (nn < HH && valid) ? Wp[kk * HH + nn] : 0.f;
    }
    g_wh[idx] = pack_h(w[0], w[1]);
}

// ================= CSR build =================
__global__ void zero_deg_kernel(int n) {
    int i = blockIdx.x * blockDim.x + threadIdx.x;
    if (i < n) g_deg[i] = 0;
}
__global__ void hist_kernel(const int* __restrict__ dst, int e) {
    int i = blockIdx.x * blockDim.x + threadIdx.x;
    if (i < e) atomicAdd(&g_deg[dst[i]], 1);
}
__global__ void scan1_kernel(int n) {
    __shared__ int sh[SC_T];
    int t = threadIdx.x, b = blockIdx.x;
    int base = b * SC_CH + t * SC_I;
    int v[SC_I];
    int run = 0;
#pragma unroll
    for (int j = 0; j < SC_I; j++) {
        int idx = base + j;
        int x = (idx < n) ? g_deg[idx] : 0;
        run += x;
        v[j] = run;
    }
    sh[t] = run;
    __syncthreads();
    for (int off = 1; off < SC_T; off <<= 1) {
        int x = (t >= off) ? sh[t - off] : 0;
        __syncthreads();
        sh[t] += x;
        __syncthreads();
    }
    int excl = sh[t] - run;
#pragma unroll
    for (int j = 0; j < SC_I; j++) {
        int idx = base + j;
        if (idx < n) g_rowptr[1 + idx] = excl + v[j];
    }
    if (t == SC_T - 1) g_part[b] = sh[t];
}
__global__ void scan2_kernel(int nb) {
    __shared__ int sh[256];
    int t = threadIdx.x;
    int v = (t < nb) ? g_part[t] : 0;
    sh[t] = v;
    __syncthreads();
    for (int off = 1; off < 256; off <<= 1) {
        int x = (t >= off) ? sh[t - off] : 0;
        __syncthreads();
        sh[t] += x;
        __syncthreads();
    }
    if (t < nb) g_part[t] = sh[t] - v;
}
__global__ void scan3_kernel(int n) {
    int idx = blockIdx.x * blockDim.x + threadIdx.x;
    if (idx < n) {
        int val = g_rowptr[1 + idx] + g_part[idx / SC_CH];
        g_rowptr[1 + idx] = val;
        if (idx + 1 < n) g_cursor[idx + 1] = val;
    }
    if (idx == 0) { g_rowptr[0] = 0; g_cursor[0] = 0; }
}
__global__ void fillcsr_kernel(const int* __restrict__ src, const int* __restrict__ dst, int e) {
    int i = blockIdx.x * blockDim.x + threadIdx.x;
    if (i < e) {
        int d = dst[i];
        int pos = atomicAdd(&g_cursor[d], 1);
        g_col[pos] = src[i];
    }
}

// ================= tensor-core GEMM (split-fp16, 2-term, cp.async pipeline) ===
// mode 0: store fp32 (+ split); mode 1: relu store fp32; mode 2: L2-norm+relu+residual (+split)
__global__ __launch_bounds__(256, 2)
void gemm_tc(const float* __restrict__ X1f,
             const uint32_t* __restrict__ Ah1, const uint32_t* __restrict__ Al1,
             const uint32_t* __restrict__ Ah2, const uint32_t* __restrict__ Al2,
             const uint32_t* __restrict__ Wh, int wstride,
             const float* __restrict__ bias,
             float* __restrict__ out, float* __restrict__ hres,
             uint32_t* __restrict__ outH, uint32_t* __restrict__ outL,
             int n, int K, int NC1, int mode) {
    extern __shared__ char sm[];
    const uint32_t sb = smem_to_u32(sm);
    const int tid = threadIdx.x;
    const int wid = tid >> 5;
    const int lane = tid & 31;
    const int row0 = blockIdx.x * 128;
    float* bias_s = (float*)(sm + SM_BIAS);

    if (tid < 112) bias_s[tid] = (tid < HH) ? bias[tid] : 0.f;

    float acc[14][4];
#pragma unroll
    for (int nt = 0; nt < 14; nt++)
#pragma unroll
        for (int q = 0; q < 4; q++) acc[nt][q] = 0.f;

    const int warp_r0 = wid * 16;
    const int a_row = warp_r0 + (lane & 15);
    const int a_kb  = (lane >> 4) * 16;
    const int b_row = lane & 7;
    const int b_kb  = ((lane >> 3) & 1) * 16;
    const int NC = K >> 6;

    // async fill of chunk c into stage s (split-A path)
    auto issue_fill = [&](int c, int s) {
        const uint32_t* srcH = (c < NC1) ? Ah1 : Ah2;
        const uint32_t* srcL = (c < NC1) ? Al1 : Al2;
        int coff = ((c < NC1) ? c : (c - NC1)) * 32;
        uint32_t base = sb + s * STG;
        for (int idx = tid; idx < 2048; idx += 256) {
            int u = idx & 7;
            int row = (idx >> 3) & 127;
            int hi = idx < 1024;
            int grow = row0 + row;
            const uint32_t* src = (hi ? srcH : srcL) + (size_t)grow * HP + coff + u * 4;
            uint32_t dst = base + (hi ? SM_AH : SM_AL) + SWZ128((uint32_t)(row * 128 + u * 16));
            cp16(dst, src, grow < n ? 16 : 0);
        }
        int kc32 = c * 32;
        for (int idx = tid; idx < 896; idx += 256) {
            int u = idx & 7;
            int nn = idx >> 3;
            const uint32_t* src = Wh + nn * wstride + kc32 + u * 4;
            uint32_t dst = base + SM_BH + SWZ128((uint32_t)(nn * 128 + u * 16));
            cp16(dst, src, 16);
        }
    };

    if (X1f) {
        // synchronous fp32 path (emb; NC small)
        for (int c = 0; c < NC; c++) {
            const int kc = c << 6;
            __syncthreads();
            for (int j = tid; j < 128 * 32; j += 256) {
                int row = j >> 5, kp = j & 31;
                int kk = kc + kp * 2;
                int grow = row0 + row;
                float x0 = 0.f, x1 = 0.f;
                if (grow < n) {
                    if (kk < K) x0 = X1f[grow * K + kk];
                    if (kk + 1 < K) x1 = X1f[grow * K + kk + 1];
                }
                uint32_t hp, lp;
                split2h(x0, x1, hp, lp);
                uint32_t off = SWZ128((uint32_t)(row * 128 + kp * 4));
                *(uint32_t*)(sm + SM_AH + off) = hp;
                *(uint32_t*)(sm + SM_AL + off) = lp;
            }
            for (int j = tid; j < 112 * 32; j += 256) {
                int nn = j >> 5, kp = j & 31;
                *(uint32_t*)(sm + SM_BH + SWZ128((uint32_t)(nn * 128 + kp * 4)))
                    = Wh[nn * wstride + (kc >> 1) + kp];
            }
            __syncthreads();
#pragma unroll
            for (int ks = 0; ks < 4; ks++) {
                uint32_t aloc = SWZ128((uint32_t)(a_row * 128 + a_kb + ks * 32));
                uint32_t ah[4], al[4];
                ldm_x4(ah, sb + SM_AH + aloc);
                ldm_x4(al, sb + SM_AL + aloc);
                uint32_t bloc = SWZ128((uint32_t)(b_row * 128 + b_kb + ks * 32));
#pragma unroll
                for (int nt = 0; nt < 14; nt++) {
                    uint32_t bh[2];
                    ldm_x2(bh, sb + SM_BH + bloc + nt * 1024);
                    mma_fp16(acc[nt], ah, bh);
                    mma_fp16(acc[nt], al, bh);
                }
            }
        }
    } else {
        // pipelined split path
        issue_fill(0, 0);
        CP_COMMIT();
        for (int c = 0; c < NC; c++) {
            int s = c & 1;
            if (c + 1 < NC) issue_fill(c + 1, s ^ 1);
            CP_COMMIT();
            CP_WAIT1();
            __syncthreads();
            uint32_t base = sb + s * STG;
#pragma unroll
            for (int ks = 0; ks < 4; ks++) {
                uint32_t aloc = SWZ128((uint32_t)(a_row * 128 + a_kb + ks * 32));
                uint32_t ah[4], al[4];
                ldm_x4(ah, base + SM_AH + aloc);
                ldm_x4(al, base + SM_AL + aloc);
                uint32_t bloc = SWZ128((uint32_t)(b_row * 128 + b_kb + ks * 32));
#pragma unroll
                for (int nt = 0; nt < 14; nt++) {
                    uint32_t bh[2];
                    ldm_x2(bh, base + SM_BH + bloc + nt * 1024);
                    mma_fp16(acc[nt], ah, bh);
                    mma_fp16(acc[nt], al, bh);
                }
            }
            if (c + 2 < NC) __syncthreads();  // stage s reused by prefetch next iter
        }
    }

    // ---- direct register epilogue ----
    const int er = warp_r0 + (lane >> 2);
    const int ec = (lane & 3) * 2;
    const int glo = row0 + er, ghi = glo + 8;
    float ss0 = 0.f, ss1 = 0.f;
#pragma unroll
    for (int nt = 0; nt < 14; nt++) {
        int col = nt * 8 + ec;
        float b0 = bias_s[col], b1 = bias_s[col + 1];
        acc[nt][0] += b0; acc[nt][1] += b1;
        acc[nt][2] += b0; acc[nt][3] += b1;
        if (mode == 2) {
            ss0 += acc[nt][0] * acc[nt][0] + acc[nt][1] * acc[nt][1];
            ss1 += acc[nt][2] * acc[nt][2] + acc[nt][3] * acc[nt][3];
        }
    }
    float s0 = 1.f, s1 = 1.f;
    if (mode == 2) {
        ss0 += __shfl_xor_sync(0xFFFFFFFFu, ss0, 1);
        ss0 += __shfl_xor_sync(0xFFFFFFFFu, ss0, 2);
        ss1 += __shfl_xor_sync(0xFFFFFFFFu, ss1, 1);
        ss1 += __shfl_xor_sync(0xFFFFFFFFu, ss1, 2);
        s0 = 1.f / fmaxf(sqrtf(ss0), 1e-12f);
        s1 = 1.f / fmaxf(sqrtf(ss1), 1e-12f);
    }
#pragma unroll
    for (int nt = 0; nt < 14; nt++) {
        int col = nt * 8 + ec;
        if (col >= HH) continue;
        float v0 = acc[nt][0], v1 = acc[nt][1], v2 = acc[nt][2], v3 = acc[nt][3];
        if (mode == 1) {
            v0 = fmaxf(v0, 0.f); v1 = fmaxf(v1, 0.f);
            v2 = fmaxf(v2, 0.f); v3 = fmaxf(v3, 0.f);
        }
        if (mode == 2) {
            if (glo < n) {
                float2 h0 = *(const float2*)(hres + (size_t)glo * HH + col);
                v0 = h0.x + fmaxf(v0 * s0, 0.f);
                v1 = h0.y + fmaxf(v1 * s0, 0.f);
            }
            if (ghi < n) {
                float2 h1 = *(const float2*)(hres + (size_t)ghi * HH + col);
                v2 = h1.x + fmaxf(v2 * s1, 0.f);
                v3 = h1.y + fmaxf(v3 * s1, 0.f);
            }
        }
        float* o_lo = (mode == 2) ? hres : out;
        if (glo < n) *(float2*)(o_lo + (size_t)glo * HH + col) = make_float2(v0, v1);
        if (ghi < n) *(float2*)(o_lo + (size_t)ghi * HH + col) = make_float2(v2, v3);
        if (outH) {
            uint32_t hp, lp;
            if (glo < n) {
                split2h(v0, v1, hp, lp);
                outH[(size_t)glo * HP + (col >> 1)] = hp;
                outL[(size_t)glo * HP + (col >> 1)] = lp;
            }
            if (ghi < n) {
                split2h(v2, v3, hp, lp);
                outH[(size_t)ghi * HP + (col >> 1)] = hp;
                outL[(size_t)ghi * HP + (col >> 1)] = lp;
            }
        }
    }
}

// ===== mean aggregation over CSR (warp/node, float4, 4-edge unroll) -> split c
__global__ void aggregate_kernel(const float* __restrict__ z,
                                 uint32_t* __restrict__ ch, uint32_t* __restrict__ cl, int n) {
    int w = (blockIdx.x * blockDim.x + threadIdx.x) >> 5;
    int lane = threadIdx.x & 31;
    if (w >= n || lane >= 27) return;
    int s = g_rowptr[w], e = g_rowptr[w + 1];
    float4 a0 = make_float4(0.f, 0.f, 0.f, 0.f);
    float4 a1 = make_float4(0.f, 0.f, 0.f, 0.f);
    int i = s;
    for (; i + 3 < e; i += 4) {
        int c0 = g_col[i], c1 = g_col[i + 1], c2 = g_col[i + 2], c3 = g_col[i + 3];
        const float4 v0 = ((const float4*)(z + (size_t)c0 * HH))[lane];
        const float4 v1 = ((const float4*)(z + (size_t)c1 * HH))[lane];
        const float4 v2 = ((const float4*)(z + (size_t)c2 * HH))[lane];
        const float4 v3 = ((const float4*)(z + (size_t)c3 * HH))[lane];
        a0.x += v0.x; a0.y += v0.y; a0.z += v0.z; a0.w += v0.w;
        a1.x += v1.x; a1.y += v1.y; a1.z += v1.z; a1.w += v1.w;
        a0.x += v2.x; a0.y += v2.y; a0.z += v2.z; a0.w += v2.w;
        a1.x += v3.x; a1.y += v3.y; a1.z += v3.z; a1.w += v3.w;
    }
    for (; i < e; i++) {
        const float4 v0 = ((const float4*)(z + (size_t)g_col[i] * HH))[lane];
        a0.x += v0.x; a0.y += v0.y; a0.z += v0.z; a0.w += v0.w;
    }
    float inv = 1.f / (float)max(e - s, 1);
    float cx = (a0.x + a1.x) * inv, cy = (a0.y + a1.y) * inv;
    float cz = (a0.z + a1.z) * inv, cw = (a0.w + a1.w) * inv;
    uint32_t hp0, lp0, hp1, lp1;
    split2h(cx, cy, hp0, lp0);
    split2h(cz, cw, hp1, lp1);
    ch[w * HP + lane * 2] = hp0;
    ch[w * HP + lane * 2 + 1] = hp1;
    cl[w * HP + lane * 2] = lp0;
    cl[w * HP + lane * 2 + 1] = lp1;
}

// ================= graph readout =================
__global__ void readout_zero_kernel(int g) {
    int i = blockIdx.x * blockDim.x + threadIdx.x;
    if (i < g * HH) g_hg[i] = 0.f;
    if (i < g) g_cnt[i] = 0.f;
}
__global__ void readout_kernel(const float* __restrict__ h, const int* __restrict__ gids, int n) {
    int w = (blockIdx.x * blockDim.x + threadIdx.x) >> 5;
    int lane = threadIdx.x & 31;
    if (w >= n) return;
    int g = gids[w];
    const float* hr = h + (size_t)w * HH;
    atomicAdd(&g_hg[g * HH + lane], hr[lane]);
    atomicAdd(&g_hg[g * HH + lane + 32], hr[lane + 32]);
    atomicAdd(&g_hg[g * HH + lane + 64], hr[lane + 64]);
    if (lane < 12) atomicAdd(&g_hg[g * HH + lane + 96], hr[lane + 96]);
    if (lane == 0) atomicAdd(&g_cnt[g], 1.f);
}
__global__ void finalize_kernel(float* __restrict__ out, int total) {
    int i = blockIdx.x * blockDim.x + threadIdx.x;
    if (i < total) out[i] = g_hg[i] / fmaxf(g_cnt[i / HH], 1.f);
}

// ================= launch =================
extern "C" void kernel_launch(void* const* d_in, const int* in_sizes, int n_in,
                              void* d_out, int out_size) {
    const float* nodes_feat = (const float*)d_in[0];
    const float* W_emb  = (const float*)d_in[4];
    const float* b_emb  = (const float*)d_in[5];
    const float* pool_W = (const float*)d_in[6];
    const float* pool_b = (const float*)d_in[7];
    const float* app_W  = (const float*)d_in[8];
    const float* app_b  = (const float*)d_in[9];
    const int* src  = (const int*)d_in[10];
    const int* dst  = (const int*)d_in[11];
    const int* gids = (const int*)d_in[12];

    const int n = in_sizes[12];
    const int e = in_sizes[10];
    const int in_dim = in_sizes[4] / HH;
    const int n_layers = in_sizes[6] / (HH * HH);
    const int G = out_size / HH;

    float *hP, *zP;
    uint32_t *hhP, *hlP, *chP, *clP, *whP;
    cudaGetSymbolAddress((void**)&hP, g_h);
    cudaGetSymbolAddress((void**)&zP, g_z);
    cudaGetSymbolAddress((void**)&hhP, g_hh);
    cudaGetSymbolAddress((void**)&hlP, g_hl);
    cudaGetSymbolAddress((void**)&chP, g_ch);
    cudaGetSymbolAddress((void**)&clP, g_cl);
    cudaGetSymbolAddress((void**)&whP, g_wh);

    cudaFuncSetAttribute(gemm_tc, cudaFuncAttributeMaxDynamicSharedMemorySize, SM_TOTAL);

    const int KPe = ((in_dim + 63) / 64) * 64;
    const int u_emb = 112 * (KPe >> 1);
    const int u_pool = 112 * 64;
    const int u_app = 112 * 128;
    const int w_total = u_emb + n_layers * (u_pool + u_app);

    const int gB = (n + 127) / 128;
    int warp_blocks = ((n * 32) + 255) / 256;

    zero_deg_kernel<<<(n + 255) / 256, 256>>>(n);                                     // 1
    hist_kernel<<<(e + 255) / 256, 256>>>(dst, e);                                    // 2
    prep_w<<<(w_total + 255) / 256, 256>>>(W_emb, in_dim, KPe, pool_W, app_W,
                                           n_layers, w_total);                        // 3
    // ---- embedding (fp32 A path), ncu capture slot #4 ----
    gemm_tc<<<gB, 256, SM_TOTAL>>>(nodes_feat,
                                   (const uint32_t*)0, (const uint32_t*)0,
                                   (const uint32_t*)0, (const uint32_t*)0,
                                   whP, KPe >> 1,
                                   b_emb, hP, (float*)0, hhP, hlP,
                                   n, KPe, 1, 0);
    // ---- CSR by dst ----
    int nb = (n + SC_CH - 1) / SC_CH;
    scan1_kernel<<<nb, SC_T>>>(n);
    scan2_kernel<<<1, 256>>>(nb);
    scan3_kernel<<<(n + 255) / 256, 256>>>(n);
    fillcsr_kernel<<<(e + 255) / 256, 256>>>(src, dst, e);

    for (int l = 0; l < n_layers; l++) {
        const float* pb = pool_b + (size_t)l * HH;
        const float* ab = app_b + (size_t)l * HH;
        const uint32_t* pWh = whP + u_emb + l * u_pool;
        const uint32_t* aWh = whP + u_emb + n_layers * u_pool + l * u_app;

        // z = relu(h @ pool_W + pool_b)   (K padded to 128, 2 chunks)
        gemm_tc<<<gB, 256, SM_TOTAL>>>((const float*)0,
                                       hhP, hlP, (const uint32_t*)0, (const uint32_t*)0,
                                       pWh, 64,
                                       pb, zP, (float*)0, (uint32_t*)0, (uint32_t*)0,
                                       n, 128, 2, 1);
        // c = mean_{u in N(v)} z[u]
        aggregate_kernel<<<warp_blocks, 256>>>(zP, chP, clP, n);
        // h += relu(l2norm([h|c] @ app_W + app_b))   (K padded to 256, 4 chunks)
        int last = (l == n_layers - 1);
        gemm_tc<<<gB, 256, SM_TOTAL>>>((const float*)0,
                                       hhP, hlP, chP, clP,
                                       aWh, 128,
                                       ab, (float*)0, hP,
                                       last ? (uint32_t*)0 : hhP,
                                       last ? (uint32_t*)0 : hlP,
                                       n, 256, 2, 2);
    }

    // ---- readout ----
    readout_zero_kernel<<<(G * HH + 255) / 256, 256>>>(G);
    readout_kernel<<<warp_blocks, 256>>>(hP, gids, n);
    finalize_kernel<<<(out_size + 255) / 256, 256>>>((float*)d_out, out_size);
}

// round 8
// speedup vs baseline: 2.5983x; 1.1235x over previous
#include <cuda_runtime.h>
#include <cuda_fp16.h>
#include <math.h>
#include <stdint.h>

#define HH 108
#define HP 64               // padded u32 pitch for split rows (256B)
#define ZP 54               // u32 pitch for packed fp16 z rows
#define NCAP 100000
#define ECAP 1600000
#define GCAP 1024
#define SC_T 256
#define SC_I 8
#define SC_CH (SC_T * SC_I)

// -------- device scratch --------
__device__ float    g_h[NCAP * HH];
__device__ float    g_z[NCAP * HH];    // reused as packed fp16 z (u32, pitch ZP)
__device__ uint32_t g_hh[NCAP * HP];
__device__ uint32_t g_hl[NCAP * HP];
__device__ uint32_t g_ch[NCAP * HP];   // also scratch for split nodes_feat before layer 0
__device__ uint32_t g_cl[NCAP * HP];
__device__ uint32_t g_wh[65536];
__device__ int   g_deg[NCAP];
__device__ int   g_rowptr[NCAP + 1];
__device__ int   g_cursor[NCAP];
__device__ int   g_col[ECAP];
__device__ int   g_part[256];
__device__ float g_hg[GCAP * HH];
__device__ float g_cnt[GCAP];

// ================= helpers =================
__device__ __forceinline__ uint32_t smem_to_u32(const void* smem_ptr) {
    uint32_t addr;
    asm("{ .reg .u64 tmp; cvta.to.shared.u64 tmp, %1; cvt.u32.u64 %0, tmp; }"
        : "=r"(addr) : "l"(smem_ptr));
    return addr;
}
__device__ __forceinline__ void ldm_x4(uint32_t* r, uint32_t addr) {
    asm volatile("ldmatrix.sync.aligned.m8n8.x4.shared.b16 {%0,%1,%2,%3}, [%4];"
        : "=r"(r[0]), "=r"(r[1]), "=r"(r[2]), "=r"(r[3]) : "r"(addr));
}
__device__ __forceinline__ void ldm_x2(uint32_t* r, uint32_t addr) {
    asm volatile("ldmatrix.sync.aligned.m8n8.x2.shared.b16 {%0,%1}, [%2];"
        : "=r"(r[0]), "=r"(r[1]) : "r"(addr));
}
__device__ __forceinline__ void mma_fp16(float* c, const uint32_t* a, const uint32_t* b) {
    asm volatile(
        "mma.sync.aligned.m16n8k16.row.col.f32.f16.f16.f32 "
        "{%0,%1,%2,%3}, {%4,%5,%6,%7}, {%8,%9}, {%0,%1,%2,%3};"
        : "+f"(c[0]), "+f"(c[1]), "+f"(c[2]), "+f"(c[3])
        : "r"(a[0]), "r"(a[1]), "r"(a[2]), "r"(a[3]), "r"(b[0]), "r"(b[1]));
}
__device__ __forceinline__ void cp16(uint32_t dst, const void* src, int sz) {
    asm volatile("cp.async.cg.shared.global [%0], [%1], 16, %2;"
                 :: "r"(dst), "l"(src), "r"(sz) : "memory");
}
#define CP_COMMIT() asm volatile("cp.async.commit_group;" ::: "memory")
#define CP_WAIT1()  asm volatile("cp.async.wait_group 1;" ::: "memory")
#define CP_WAIT0()  asm volatile("cp.async.wait_group 0;" ::: "memory")
#define SWZ128(b) ((b) ^ (((b) >> 3) & 0x70))

__device__ __forceinline__ void split2h(float x, float y, uint32_t& hp, uint32_t& lp) {
    __half hx = __float2half_rn(x), hy = __float2half_rn(y);
    float lx = x - __half2float(hx), ly = y - __half2float(hy);
    hp = ((uint32_t)__half_as_ushort(hy) << 16) | __half_as_ushort(hx);
    lp = ((uint32_t)__half_as_ushort(__float2half_rn(ly)) << 16)
       | __half_as_ushort(__float2half_rn(lx));
}
__device__ __forceinline__ uint32_t pack_h(float x, float y) {
    return ((uint32_t)__half_as_ushort(__float2half_rn(y)) << 16)
         | __half_as_ushort(__float2half_rn(x));
}

// ================= smem layout: double-buffered stages =================
#define SM_BIAS 0
#define SM_AH   1024
#define SM_AL   (SM_AH + 16384)
#define SM_BH   (SM_AL + 16384)
#define STG     47104
#define SM_TOTAL (1024 + 2 * STG)   // 95232

// ================= weight prep =================
__global__ void prep_w(const float* __restrict__ W_emb, int Kemb, int KPe,
                       const float* __restrict__ pool_W,
                       const float* __restrict__ app_W, int n_layers, int total) {
    int idx = blockIdx.x * blockDim.x + threadIdx.x;
    if (idx >= total) return;
    const float* Wp = 0;
    int K = 0, KP = 0, rel = idx, off = 0, is_app = 0;
    int sz = 112 * (KPe >> 1);
    if (idx < sz) { Wp = W_emb; K = Kemb; KP = KPe; rel = idx; }
    else {
        off = sz;
        for (int l = 0; l < n_layers && !Wp; l++) {
            if (idx < off + 112 * 64) { Wp = pool_W + l * HH * HH; K = HH; KP = 128; rel = idx - off; }
            off += 112 * 64;
        }
        for (int l = 0; l < n_layers && !Wp; l++) {
            if (idx < off + 112 * 128) { Wp = app_W + l * 2 * HH * HH; K = 2 * HH; KP = 256; rel = idx - off; is_app = 1; }
            off += 112 * 128;
        }
        if (!Wp) return;
    }
    int nn = rel / (KP >> 1);
    int kp = rel - nn * (KP >> 1);
    float w[2];
#pragma unroll
    for (int q = 0; q < 2; q++) {
        int k = kp * 2 + q;
        int kk, valid;
        if (is_app) {
            if (k < 128) { kk = k; valid = (k < HH); }
            else { kk = HH + (k - 128); valid = (k - 128 < HH); }
        } else { kk = k; valid = (k < K); }
        w[q] = (nn < HH && valid) ? Wp[kk * HH + nn] : 0.f;
    }
    g_wh[idx] = pack_h(w[0], w[1]);
}

// ================= split nodes_feat into (xh, xl), pitch KPe/2 ================
__global__ void prep_x(const float* __restrict__ X, int in_dim, int KPe,
                       uint32_t* __restrict__ xh, uint32_t* __restrict__ xl, int total) {
    int idx = blockIdx.x * blockDim.x + threadIdx.x;
    if (idx >= total) return;
    int pu = KPe >> 1;
    int row = idx / pu;
    int kp = idx - row * pu;
    int k0 = kp * 2;
    float x0 = (k0 < in_dim) ? X[(size_t)row * in_dim + k0] : 0.f;
    float x1 = (k0 + 1 < in_dim) ? X[(size_t)row * in_dim + k0 + 1] : 0.f;
    uint32_t hp, lp;
    split2h(x0, x1, hp, lp);
    xh[idx] = hp;
    xl[idx] = lp;
}

// ================= CSR build =================
__global__ void zero_deg_kernel(int n) {
    int i = blockIdx.x * blockDim.x + threadIdx.x;
    if (i < n) g_deg[i] = 0;
}
__global__ void hist_kernel(const int* __restrict__ dst, int e) {
    int i = blockIdx.x * blockDim.x + threadIdx.x;
    if (i < e) atomicAdd(&g_deg[dst[i]], 1);
}
__global__ void scan1_kernel(int n) {
    __shared__ int sh[SC_T];
    int t = threadIdx.x, b = blockIdx.x;
    int base = b * SC_CH + t * SC_I;
    int v[SC_I];
    int run = 0;
#pragma unroll
    for (int j = 0; j < SC_I; j++) {
        int idx = base + j;
        int x = (idx < n) ? g_deg[idx] : 0;
        run += x;
        v[j] = run;
    }
    sh[t] = run;
    __syncthreads();
    for (int off = 1; off < SC_T; off <<= 1) {
        int x = (t >= off) ? sh[t - off] : 0;
        __syncthreads();
        sh[t] += x;
        __syncthreads();
    }
    int excl = sh[t] - run;
#pragma unroll
    for (int j = 0; j < SC_I; j++) {
        int idx = base + j;
        if (idx < n) g_rowptr[1 + idx] = excl + v[j];
    }
    if (t == SC_T - 1) g_part[b] = sh[t];
}
__global__ void scan2_kernel(int nb) {
    __shared__ int sh[256];
    int t = threadIdx.x;
    int v = (t < nb) ? g_part[t] : 0;
    sh[t] = v;
    __syncthreads();
    for (int off = 1; off < 256; off <<= 1) {
        int x = (t >= off) ? sh[t - off] : 0;
        __syncthreads();
        sh[t] += x;
        __syncthreads();
    }
    if (t < nb) g_part[t] = sh[t] - v;
}
__global__ void scan3_kernel(int n) {
    int idx = blockIdx.x * blockDim.x + threadIdx.x;
    if (idx < n) {
        int val = g_rowptr[1 + idx] + g_part[idx / SC_CH];
        g_rowptr[1 + idx] = val;
        if (idx + 1 < n) g_cursor[idx + 1] = val;
    }
    if (idx == 0) { g_rowptr[0] = 0; g_cursor[0] = 0; }
}
__global__ void fillcsr_kernel(const int* __restrict__ src, const int* __restrict__ dst, int e) {
    int i = blockIdx.x * blockDim.x + threadIdx.x;
    if (i < e) {
        int d = dst[i];
        int pos = atomicAdd(&g_cursor[d], 1);
        g_col[pos] = src[i];
    }
}

// ================= tensor-core GEMM (split-fp16, 2-term, cp.async pipeline) ===
// mode 0: store fp32 out + split outH/outL
// mode 2: L2-norm + relu + residual into hres (+ split)
// mode 3: relu + pack fp16 -> (uint32_t*)out, pitch ZP
__global__ __launch_bounds__(256, 2)
void gemm_tc(const uint32_t* __restrict__ Ah1, const uint32_t* __restrict__ Al1,
             const uint32_t* __restrict__ Ah2, const uint32_t* __restrict__ Al2,
             int NC1, int apitch,
             const uint32_t* __restrict__ Wh, int wstride,
             const float* __restrict__ bias,
             float* __restrict__ out, float* __restrict__ hres,
             uint32_t* __restrict__ outH, uint32_t* __restrict__ outL,
             int n, int K, int mode) {
    extern __shared__ char sm[];
    const uint32_t sb = smem_to_u32(sm);
    const int tid = threadIdx.x;
    const int wid = tid >> 5;
    const int lane = tid & 31;
    const int row0 = blockIdx.x * 128;
    float* bias_s = (float*)(sm + SM_BIAS);

    if (tid < 112) bias_s[tid] = (tid < HH) ? bias[tid] : 0.f;

    float acc[14][4];
#pragma unroll
    for (int nt = 0; nt < 14; nt++)
#pragma unroll
        for (int q = 0; q < 4; q++) acc[nt][q] = 0.f;

    const int warp_r0 = wid * 16;
    const int a_row = warp_r0 + (lane & 15);
    const int a_kb  = (lane >> 4) * 16;
    const int b_row = lane & 7;
    const int b_kb  = ((lane >> 3) & 1) * 16;
    const int NC = K >> 6;

    auto issue_fill = [&](int c, int s) {
        const uint32_t* srcH = (c < NC1) ? Ah1 : Ah2;
        const uint32_t* srcL = (c < NC1) ? Al1 : Al2;
        int coff = ((c < NC1) ? c : (c - NC1)) * 32;
        uint32_t base = sb + s * STG;
        for (int idx = tid; idx < 2048; idx += 256) {
            int u = idx & 7;
            int row = (idx >> 3) & 127;
            int hi = idx < 1024;
            int grow = row0 + row;
            const uint32_t* src = (hi ? srcH : srcL) + (size_t)grow * apitch + coff + u * 4;
            uint32_t dst = base + (hi ? SM_AH : SM_AL) + SWZ128((uint32_t)(row * 128 + u * 16));
            cp16(dst, src, grow < n ? 16 : 0);
        }
        int kc32 = c * 32;
        for (int idx = tid; idx < 896; idx += 256) {
            int u = idx & 7;
            int nn = idx >> 3;
            const uint32_t* src = Wh + nn * wstride + kc32 + u * 4;
            uint32_t dst = base + SM_BH + SWZ128((uint32_t)(nn * 128 + u * 16));
            cp16(dst, src, 16);
        }
    };

    issue_fill(0, 0);
    CP_COMMIT();
    for (int c = 0; c < NC; c++) {
        int s = c & 1;
        if (c + 1 < NC) {
            issue_fill(c + 1, s ^ 1);
            CP_COMMIT();
            CP_WAIT1();
        } else {
            CP_WAIT0();
        }
        __syncthreads();
        uint32_t base = sb + s * STG;
#pragma unroll
        for (int ks = 0; ks < 4; ks++) {
            uint32_t aloc = SWZ128((uint32_t)(a_row * 128 + a_kb + ks * 32));
            uint32_t ah[4], al[4];
            ldm_x4(ah, base + SM_AH + aloc);
            ldm_x4(al, base + SM_AL + aloc);
            uint32_t bloc = SWZ128((uint32_t)(b_row * 128 + b_kb + ks * 32));
#pragma unroll
            for (int nt = 0; nt < 14; nt++) {
                uint32_t bh[2];
                ldm_x2(bh, base + SM_BH + bloc + nt * 1024);
                mma_fp16(acc[nt], ah, bh);
                mma_fp16(acc[nt], al, bh);
            }
        }
        if (c + 2 < NC) __syncthreads();
    }

    // ---- direct register epilogue ----
    const int er = warp_r0 + (lane >> 2);
    const int ec = (lane & 3) * 2;
    const int glo = row0 + er, ghi = glo + 8;
    float ss0 = 0.f, ss1 = 0.f;
#pragma unroll
    for (int nt = 0; nt < 14; nt++) {
        int col = nt * 8 + ec;
        float b0 = bias_s[col], b1 = bias_s[col + 1];
        acc[nt][0] += b0; acc[nt][1] += b1;
        acc[nt][2] += b0; acc[nt][3] += b1;
        if (mode == 2) {
            ss0 += acc[nt][0] * acc[nt][0] + acc[nt][1] * acc[nt][1];
            ss1 += acc[nt][2] * acc[nt][2] + acc[nt][3] * acc[nt][3];
        }
    }
    float s0 = 1.f, s1 = 1.f;
    if (mode == 2) {
        ss0 += __shfl_xor_sync(0xFFFFFFFFu, ss0, 1);
        ss0 += __shfl_xor_sync(0xFFFFFFFFu, ss0, 2);
        ss1 += __shfl_xor_sync(0xFFFFFFFFu, ss1, 1);
        ss1 += __shfl_xor_sync(0xFFFFFFFFu, ss1, 2);
        s0 = 1.f / fmaxf(sqrtf(ss0), 1e-12f);
        s1 = 1.f / fmaxf(sqrtf(ss1), 1e-12f);
    }
#pragma unroll
    for (int nt = 0; nt < 14; nt++) {
        int col = nt * 8 + ec;
        if (col >= HH) continue;
        float v0 = acc[nt][0], v1 = acc[nt][1], v2 = acc[nt][2], v3 = acc[nt][3];
        if (mode == 3) {
            v0 = fmaxf(v0, 0.f); v1 = fmaxf(v1, 0.f);
            v2 = fmaxf(v2, 0.f); v3 = fmaxf(v3, 0.f);
            uint32_t* zo = (uint32_t*)out;
            if (glo < n) zo[(size_t)glo * ZP + (col >> 1)] = pack_h(v0, v1);
            if (ghi < n) zo[(size_t)ghi * ZP + (col >> 1)] = pack_h(v2, v3);
            continue;
        }
        if (mode == 2) {
            if (glo < n) {
                float2 h0 = *(const float2*)(hres + (size_t)glo * HH + col);
                v0 = h0.x + fmaxf(v0 * s0, 0.f);
                v1 = h0.y + fmaxf(v1 * s0, 0.f);
            }
            if (ghi < n) {
                float2 h1 = *(const float2*)(hres + (size_t)ghi * HH + col);
                v2 = h1.x + fmaxf(v2 * s1, 0.f);
                v3 = h1.y + fmaxf(v3 * s1, 0.f);
            }
        }
        float* o_lo = (mode == 2) ? hres : out;
        if (glo < n) *(float2*)(o_lo + (size_t)glo * HH + col) = make_float2(v0, v1);
        if (ghi < n) *(float2*)(o_lo + (size_t)ghi * HH + col) = make_float2(v2, v3);
        if (outH) {
            uint32_t hp, lp;
            if (glo < n) {
                split2h(v0, v1, hp, lp);
                outH[(size_t)glo * HP + (col >> 1)] = hp;
                outL[(size_t)glo * HP + (col >> 1)] = lp;
            }
            if (ghi < n) {
                split2h(v2, v3, hp, lp);
                outH[(size_t)ghi * HP + (col >> 1)] = hp;
                outL[(size_t)ghi * HP + (col >> 1)] = lp;
            }
        }
    }
}

// ===== mean aggregation over CSR: z packed fp16 (pitch ZP) -> split c (pitch HP)
__global__ void aggregate_kernel(const uint32_t* __restrict__ zp,
                                 uint32_t* __restrict__ ch, uint32_t* __restrict__ cl, int n) {
    int w = (blockIdx.x * blockDim.x + threadIdx.x) >> 5;
    int lane = threadIdx.x & 31;
    if (w >= n || lane >= 27) return;
    int s = g_rowptr[w], e = g_rowptr[w + 1];
    float a0 = 0.f, a1 = 0.f, a2 = 0.f, a3 = 0.f;
    int i = s;
    for (; i + 3 < e; i += 4) {
        int c0 = g_col[i], c1 = g_col[i + 1], c2 = g_col[i + 2], c3 = g_col[i + 3];
        uint2 u0 = ((const uint2*)(zp + (size_t)c0 * ZP))[lane];
        uint2 u1 = ((const uint2*)(zp + (size_t)c1 * ZP))[lane];
        uint2 u2 = ((const uint2*)(zp + (size_t)c2 * ZP))[lane];
        uint2 u3 = ((const uint2*)(zp + (size_t)c3 * ZP))[lane];
        float2 f;
        f = __half22float2(*(__half2*)&u0.x); a0 += f.x; a1 += f.y;
        f = __half22float2(*(__half2*)&u0.y); a2 += f.x; a3 += f.y;
        f = __half22float2(*(__half2*)&u1.x); a0 += f.x; a1 += f.y;
        f = __half22float2(*(__half2*)&u1.y); a2 += f.x; a3 += f.y;
        f = __half22float2(*(__half2*)&u2.x); a0 += f.x; a1 += f.y;
        f = __half22float2(*(__half2*)&u2.y); a2 += f.x; a3 += f.y;
        f = __half22float2(*(__half2*)&u3.x); a0 += f.x; a1 += f.y;
        f = __half22float2(*(__half2*)&u3.y); a2 += f.x; a3 += f.y;
    }
    for (; i < e; i++) {
        uint2 u0 = ((const uint2*)(zp + (size_t)g_col[i] * ZP))[lane];
        float2 f;
        f = __half22float2(*(__half2*)&u0.x); a0 += f.x; a1 += f.y;
        f = __half22float2(*(__half2*)&u0.y); a2 += f.x; a3 += f.y;
    }
    float inv = 1.f / (float)max(e - s, 1);
    uint32_t hp0, lp0, hp1, lp1;
    split2h(a0 * inv, a1 * inv, hp0, lp0);
    split2h(a2 * inv, a3 * inv, hp1, lp1);
    ch[(size_t)w * HP + lane * 2] = hp0;
    ch[(size_t)w * HP + lane * 2 + 1] = hp1;
    cl[(size_t)w * HP + lane * 2] = lp0;
    cl[(size_t)w * HP + lane * 2 + 1] = lp1;
}

// ================= graph readout =================
__global__ void readout_zero_kernel(int g) {
    int i = blockIdx.x * blockDim.x + threadIdx.x;
    if (i < g * HH) g_hg[i] = 0.f;
    if (i < g) g_cnt[i] = 0.f;
}
__global__ void readout_kernel(const float* __restrict__ h, const int* __restrict__ gids, int n) {
    int w = (blockIdx.x * blockDim.x + threadIdx.x) >> 5;
    int lane = threadIdx.x & 31;
    if (w >= n) return;
    int g = gids[w];
    const float* hr = h + (size_t)w * HH;
    atomicAdd(&g_hg[g * HH + lane], hr[lane]);
    atomicAdd(&g_hg[g * HH + lane + 32], hr[lane + 32]);
    atomicAdd(&g_hg[g * HH + lane + 64], hr[lane + 64]);
    if (lane < 12) atomicAdd(&g_hg[g * HH + lane + 96], hr[lane + 96]);
    if (lane == 0) atomicAdd(&g_cnt[g], 1.f);
}
__global__ void finalize_kernel(float* __restrict__ out, int total) {
    int i = blockIdx.x * blockDim.x + threadIdx.x;
    if (i < total) out[i] = g_hg[i] / fmaxf(g_cnt[i / HH], 1.f);
}

// ================= launch =================
extern "C" void kernel_launch(void* const* d_in, const int* in_sizes, int n_in,
                              void* d_out, int out_size) {
    const float* nodes_feat = (const float*)d_in[0];
    const float* W_emb  = (const float*)d_in[4];
    const float* b_emb  = (const float*)d_in[5];
    const float* pool_W = (const float*)d_in[6];
    const float* pool_b = (const float*)d_in[7];
    const float* app_W  = (const float*)d_in[8];
    const float* app_b  = (const float*)d_in[9];
    const int* src  = (const int*)d_in[10];
    const int* dst  = (const int*)d_in[11];
    const int* gids = (const int*)d_in[12];

    const int n = in_sizes[12];
    const int e = in_sizes[10];
    const int in_dim = in_sizes[4] / HH;
    const int n_layers = in_sizes[6] / (HH * HH);
    const int G = out_size / HH;

    float *hP, *zP;
    uint32_t *hhP, *hlP, *chP, *clP, *whP;
    cudaGetSymbolAddress((void**)&hP, g_h);
    cudaGetSymbolAddress((void**)&zP, g_z);
    cudaGetSymbolAddress((void**)&hhP, g_hh);
    cudaGetSymbolAddress((void**)&hlP, g_hl);
    cudaGetSymbolAddress((void**)&chP, g_ch);
    cudaGetSymbolAddress((void**)&clP, g_cl);
    cudaGetSymbolAddress((void**)&whP, g_wh);

    cudaFuncSetAttribute(gemm_tc, cudaFuncAttributeMaxDynamicSharedMemorySize, SM_TOTAL);

    const int KPe = ((in_dim + 63) / 64) * 64;
    const int u_emb = 112 * (KPe >> 1);
    const int u_pool = 112 * 64;
    const int u_app = 112 * 128;
    const int w_total = u_emb + n_layers * (u_pool + u_app);
    const int x_total = n * (KPe >> 1);

    const int gB = (n + 127) / 128;
    int warp_blocks = ((n * 32) + 255) / 256;

    zero_deg_kernel<<<(n + 255) / 256, 256>>>(n);                                   // 1
    prep_w<<<(w_total + 255) / 256, 256>>>(W_emb, in_dim, KPe, pool_W, app_W,
                                           n_layers, w_total);                      // 2
    prep_x<<<(x_total + 255) / 256, 256>>>(nodes_feat, in_dim, KPe, chP, clP,
                                           x_total);                                // 3
    // ---- embedding: h = X @ W_emb + b_emb (async split path), capture slot #4
    gemm_tc<<<gB, 256, SM_TOTAL>>>(chP, clP, (const uint32_t*)0, (const uint32_t*)0,
                                   KPe >> 6, KPe >> 1,
                                   whP, KPe >> 1,
                                   b_emb, hP, (float*)0, hhP, hlP,
                                   n, KPe, 0);                                      // 4
    // ---- CSR by dst ----
    hist_kernel<<<(e + 255) / 256, 256>>>(dst, e);
    int nb = (n + SC_CH - 1) / SC_CH;
    scan1_kernel<<<nb, SC_T>>>(n);
    scan2_kernel<<<1, 256>>>(nb);
    scan3_kernel<<<(n + 255) / 256, 256>>>(n);
    fillcsr_kernel<<<(e + 255) / 256, 256>>>(src, dst, e);

    for (int l = 0; l < n_layers; l++) {
        const float* pb = pool_b + (size_t)l * HH;
        const float* ab = app_b + (size_t)l * HH;
        const uint32_t* pWh = whP + u_emb + l * u_pool;
        const uint32_t* aWh = whP + u_emb + n_layers * u_pool + l * u_app;

        // z = relu(h @ pool_W + pool_b) -> packed fp16, pitch ZP
        gemm_tc<<<gB, 256, SM_TOTAL>>>(hhP, hlP, (const uint32_t*)0, (const uint32_t*)0,
                                       2, HP,
                                       pWh, 64,
                                       pb, zP, (float*)0, (uint32_t*)0, (uint32_t*)0,
                                       n, 128, 3);
        // c = mean_{u in N(v)} z[u]
        aggregate_kernel<<<warp_blocks, 256>>>((const uint32_t*)zP, chP, clP, n);
        // h += relu(l2norm([h|c] @ app_W + app_b))
        int last = (l == n_layers - 1);
        gemm_tc<<<gB, 256, SM_TOTAL>>>(hhP, hlP, chP, clP,
                                       2, HP,
                                       aWh, 128,
                                       ab, (float*)0, hP,
                                       last ? (uint32_t*)0 : hhP,
                                       last ? (uint32_t*)0 : hlP,
                                       n, 256, 2);
    }

    // ---- readout ----
    readout_zero_kernel<<<(G * HH + 255) / 256, 256>>>(G);
    readout_kernel<<<warp_blocks, 256>>>(hP, gids, n);
    finalize_kernel<<<(out_size + 255) / 256, 256>>>((float*)d_out, out_size);
}

// round 9
// speedup vs baseline: 2.7926x; 1.0748x over previous
#include <cuda_runtime.h>
#include <cuda_fp16.h>
#include <math.h>
#include <stdint.h>

#define HH 108
#define HP 64               // padded u32 pitch for split rows (256B)
#define ZP 54               // u32 pitch for packed fp16 z rows
#define NCAP 100000
#define ECAP 1600000
#define GCAP 1024
#define SC_T 256
#define SC_I 8
#define SC_CH (SC_T * SC_I)

// -------- device scratch --------
__device__ float    g_h[NCAP * HH];
__device__ float    g_z[NCAP * HH];    // reused as packed fp16 z (u32, pitch ZP)
__device__ uint32_t g_hh[NCAP * HP];
__device__ uint32_t g_hl[NCAP * HP];
__device__ uint32_t g_ch[NCAP * HP];   // also scratch for split nodes_feat before layer 0
__device__ uint32_t g_cl[NCAP * HP];
__device__ uint32_t g_wh[65536];
__device__ int   g_deg[NCAP];
__device__ int   g_rowptr[NCAP + 1];
__device__ int   g_cursor[NCAP];
__device__ int   g_col[ECAP];
__device__ int   g_part[256];
__device__ float g_hg[GCAP * HH];
__device__ float g_cnt[GCAP];

// ================= helpers =================
__device__ __forceinline__ uint32_t smem_to_u32(const void* smem_ptr) {
    uint32_t addr;
    asm("{ .reg .u64 tmp; cvta.to.shared.u64 tmp, %1; cvt.u32.u64 %0, tmp; }"
        : "=r"(addr) : "l"(smem_ptr));
    return addr;
}
__device__ __forceinline__ void ldm_x4(uint32_t* r, uint32_t addr) {
    asm volatile("ldmatrix.sync.aligned.m8n8.x4.shared.b16 {%0,%1,%2,%3}, [%4];"
        : "=r"(r[0]), "=r"(r[1]), "=r"(r[2]), "=r"(r[3]) : "r"(addr));
}
__device__ __forceinline__ void ldm_x2(uint32_t* r, uint32_t addr) {
    asm volatile("ldmatrix.sync.aligned.m8n8.x2.shared.b16 {%0,%1}, [%2];"
        : "=r"(r[0]), "=r"(r[1]) : "r"(addr));
}
__device__ __forceinline__ void mma_fp16(float* c, const uint32_t* a, const uint32_t* b) {
    asm volatile(
        "mma.sync.aligned.m16n8k16.row.col.f32.f16.f16.f32 "
        "{%0,%1,%2,%3}, {%4,%5,%6,%7}, {%8,%9}, {%0,%1,%2,%3};"
        : "+f"(c[0]), "+f"(c[1]), "+f"(c[2]), "+f"(c[3])
        : "r"(a[0]), "r"(a[1]), "r"(a[2]), "r"(a[3]), "r"(b[0]), "r"(b[1]));
}
__device__ __forceinline__ void cp16(uint32_t dst, const void* src, int sz) {
    asm volatile("cp.async.cg.shared.global [%0], [%1], 16, %2;"
                 :: "r"(dst), "l"(src), "r"(sz) : "memory");
}
#define CP_COMMIT() asm volatile("cp.async.commit_group;" ::: "memory")
#define CP_WAIT1()  asm volatile("cp.async.wait_group 1;" ::: "memory")
#define CP_WAIT0()  asm volatile("cp.async.wait_group 0;" ::: "memory")
#define SWZ128(b) ((b) ^ (((b) >> 3) & 0x70))

__device__ __forceinline__ void split2h(float x, float y, uint32_t& hp, uint32_t& lp) {
    __half hx = __float2half_rn(x), hy = __float2half_rn(y);
    float lx = x - __half2float(hx), ly = y - __half2float(hy);
    hp = ((uint32_t)__half_as_ushort(hy) << 16) | __half_as_ushort(hx);
    lp = ((uint32_t)__half_as_ushort(__float2half_rn(ly)) << 16)
       | __half_as_ushort(__float2half_rn(lx));
}
__device__ __forceinline__ uint32_t pack_h(float x, float y) {
    return ((uint32_t)__half_as_ushort(__float2half_rn(y)) << 16)
         | __half_as_ushort(__float2half_rn(x));
}

// ================= smem layout: 64-row tiles, double-buffered =================
#define SM_BIAS 0        // 112 floats
#define SM_NRM  512      // 64 x 2 floats
#define SM_AH   1024     // 64 x 128B = 8192
#define SM_AL   (SM_AH + 8192)
#define SM_BH   (SM_AL + 8192)   // 112 x 128B = 14336
#define STG     30720
#define SM_TOTAL (1024 + 2 * STG)   // 62464 -> 3 CTAs/SM

// ================= weight prep =================
__global__ void prep_w(const float* __restrict__ W_emb, int Kemb, int KPe,
                       const float* __restrict__ pool_W,
                       const float* __restrict__ app_W, int n_layers, int total) {
    int idx = blockIdx.x * blockDim.x + threadIdx.x;
    if (idx >= total) return;
    const float* Wp = 0;
    int K = 0, KP = 0, rel = idx, off = 0, is_app = 0;
    int sz = 112 * (KPe >> 1);
    if (idx < sz) { Wp = W_emb; K = Kemb; KP = KPe; rel = idx; }
    else {
        off = sz;
        for (int l = 0; l < n_layers && !Wp; l++) {
            if (idx < off + 112 * 64) { Wp = pool_W + l * HH * HH; K = HH; KP = 128; rel = idx - off; }
            off += 112 * 64;
        }
        for (int l = 0; l < n_layers && !Wp; l++) {
            if (idx < off + 112 * 128) { Wp = app_W + l * 2 * HH * HH; K = 2 * HH; KP = 256; rel = idx - off; is_app = 1; }
            off += 112 * 128;
        }
        if (!Wp) return;
    }
    int nn = rel / (KP >> 1);
    int kp = rel - nn * (KP >> 1);
    float w[2];
#pragma unroll
    for (int q = 0; q < 2; q++) {
        int k = kp * 2 + q;
        int kk, valid;
        if (is_app) {
            if (k < 128) { kk = k; valid = (k < HH); }
            else { kk = HH + (k - 128); valid = (k - 128 < HH); }
        } else { kk = k; valid = (k < K); }
        w[q] = (nn < HH && valid) ? Wp[kk * HH + nn] : 0.f;
    }
    g_wh[idx] = pack_h(w[0], w[1]);
}

// ================= split nodes_feat into (xh, xl), pitch KPe/2 ================
__global__ void prep_x(const float* __restrict__ X, int in_dim, int KPe,
                       uint32_t* __restrict__ xh, uint32_t* __restrict__ xl, int total) {
    int idx = blockIdx.x * blockDim.x + threadIdx.x;
    if (idx >= total) return;
    int pu = KPe >> 1;
    int row = idx / pu;
    int kp = idx - row * pu;
    int k0 = kp * 2;
    float x0 = (k0 < in_dim) ? X[(size_t)row * in_dim + k0] : 0.f;
    float x1 = (k0 + 1 < in_dim) ? X[(size_t)row * in_dim + k0 + 1] : 0.f;
    uint32_t hp, lp;
    split2h(x0, x1, hp, lp);
    xh[idx] = hp;
    xl[idx] = lp;
}

// ================= CSR build =================
__global__ void zero_deg_kernel(int n) {
    int i = blockIdx.x * blockDim.x + threadIdx.x;
    if (i < n) g_deg[i] = 0;
}
__global__ void hist_kernel(const int* __restrict__ dst, int e) {
    int i = blockIdx.x * blockDim.x + threadIdx.x;
    if (i < e) atomicAdd(&g_deg[dst[i]], 1);
}
__global__ void scan1_kernel(int n) {
    __shared__ int sh[SC_T];
    int t = threadIdx.x, b = blockIdx.x;
    int base = b * SC_CH + t * SC_I;
    int v[SC_I];
    int run = 0;
#pragma unroll
    for (int j = 0; j < SC_I; j++) {
        int idx = base + j;
        int x = (idx < n) ? g_deg[idx] : 0;
        run += x;
        v[j] = run;
    }
    sh[t] = run;
    __syncthreads();
    for (int off = 1; off < SC_T; off <<= 1) {
        int x = (t >= off) ? sh[t - off] : 0;
        __syncthreads();
        sh[t] += x;
        __syncthreads();
    }
    int excl = sh[t] - run;
#pragma unroll
    for (int j = 0; j < SC_I; j++) {
        int idx = base + j;
        if (idx < n) g_rowptr[1 + idx] = excl + v[j];
    }
    if (t == SC_T - 1) g_part[b] = sh[t];
}
__global__ void scan2_kernel(int nb) {
    __shared__ int sh[256];
    int t = threadIdx.x;
    int v = (t < nb) ? g_part[t] : 0;
    sh[t] = v;
    __syncthreads();
    for (int off = 1; off < 256; off <<= 1) {
        int x = (t >= off) ? sh[t - off] : 0;
        __syncthreads();
        sh[t] += x;
        __syncthreads();
    }
    if (t < nb) g_part[t] = sh[t] - v;
}
__global__ void scan3_kernel(int n) {
    int idx = blockIdx.x * blockDim.x + threadIdx.x;
    if (idx < n) {
        int val = g_rowptr[1 + idx] + g_part[idx / SC_CH];
        g_rowptr[1 + idx] = val;
        if (idx + 1 < n) g_cursor[idx + 1] = val;
    }
    if (idx == 0) { g_rowptr[0] = 0; g_cursor[0] = 0; }
}
__global__ void fillcsr_kernel(const int* __restrict__ src, const int* __restrict__ dst, int e) {
    int i = blockIdx.x * blockDim.x + threadIdx.x;
    if (i < e) {
        int d = dst[i];
        int pos = atomicAdd(&g_cursor[d], 1);
        g_col[pos] = src[i];
    }
}

// ================= tensor-core GEMM: 64-row tile, 8 warps = 4 rowgrp x 2 colhalf
// mode 0: store fp32 out + split outH/outL
// mode 2: L2-norm + relu + residual into hres (+ split)
// mode 3: relu + pack fp16 -> (uint32_t*)out, pitch ZP
__global__ __launch_bounds__(256, 3)
void gemm_tc(const uint32_t* __restrict__ Ah1, const uint32_t* __restrict__ Al1,
             const uint32_t* __restrict__ Ah2, const uint32_t* __restrict__ Al2,
             int NC1, int apitch,
             const uint32_t* __restrict__ Wh, int wstride,
             const float* __restrict__ bias,
             float* __restrict__ out, float* __restrict__ hres,
             uint32_t* __restrict__ outH, uint32_t* __restrict__ outL,
             int n, int K, int mode) {
    extern __shared__ char sm[];
    const uint32_t sb = smem_to_u32(sm);
    const int tid = threadIdx.x;
    const int wid = tid >> 5;
    const int lane = tid & 31;
    const int row0 = blockIdx.x * 64;
    float* bias_s = (float*)(sm + SM_BIAS);
    float* nrm_s  = (float*)(sm + SM_NRM);

    if (tid < 112) bias_s[tid] = (tid < HH) ? bias[tid] : 0.f;

    const int rg = wid & 3;       // row group (16 rows)
    const int colh = wid >> 2;    // N half (56 cols)
    const int warp_r0 = rg * 16;

    float acc[7][4];
#pragma unroll
    for (int nt = 0; nt < 7; nt++)
#pragma unroll
        for (int q = 0; q < 4; q++) acc[nt][q] = 0.f;

    const int a_row = warp_r0 + (lane & 15);
    const int a_kb  = (lane >> 4) * 16;
    const int b_row = lane & 7;
    const int b_kb  = ((lane >> 3) & 1) * 16;
    const int NC = K >> 6;

    auto issue_fill = [&](int c, int s) {
        const uint32_t* srcH = (c < NC1) ? Ah1 : Ah2;
        const uint32_t* srcL = (c < NC1) ? Al1 : Al2;
        int coff = ((c < NC1) ? c : (c - NC1)) * 32;
        uint32_t base = sb + s * STG;
        // A: 64 rows x (hi,lo) x 8 16B-units = 1024 cp16
        for (int idx = tid; idx < 1024; idx += 256) {
            int u = idx & 7;
            int row = (idx >> 3) & 63;
            int hi = idx < 512;
            int grow = row0 + row;
            const uint32_t* src = (hi ? srcH : srcL) + (size_t)grow * apitch + coff + u * 4;
            uint32_t dst = base + (hi ? SM_AH : SM_AL) + SWZ128((uint32_t)(row * 128 + u * 16));
            cp16(dst, src, grow < n ? 16 : 0);
        }
        int kc32 = c * 32;
        for (int idx = tid; idx < 896; idx += 256) {
            int u = idx & 7;
            int nn = idx >> 3;
            const uint32_t* src = Wh + nn * wstride + kc32 + u * 4;
            uint32_t dst = base + SM_BH + SWZ128((uint32_t)(nn * 128 + u * 16));
            cp16(dst, src, 16);
        }
    };

    issue_fill(0, 0);
    CP_COMMIT();
    for (int c = 0; c < NC; c++) {
        int s = c & 1;
        if (c + 1 < NC) {
            issue_fill(c + 1, s ^ 1);
            CP_COMMIT();
            CP_WAIT1();
        } else {
            CP_WAIT0();
        }
        __syncthreads();
        uint32_t base = sb + s * STG;
#pragma unroll
        for (int ks = 0; ks < 4; ks++) {
            uint32_t aloc = SWZ128((uint32_t)(a_row * 128 + a_kb + ks * 32));
            uint32_t ah[4], al[4];
            ldm_x4(ah, base + SM_AH + aloc);
            ldm_x4(al, base + SM_AL + aloc);
            uint32_t bloc = SWZ128((uint32_t)(b_row * 128 + b_kb + ks * 32));
#pragma unroll
            for (int nt = 0; nt < 7; nt++) {
                uint32_t bh[2];
                ldm_x2(bh, base + SM_BH + bloc + (colh * 7 + nt) * 1024);
                mma_fp16(acc[nt], ah, bh);
                mma_fp16(acc[nt], al, bh);
            }
        }
        if (c + 2 < NC) __syncthreads();
    }

    // ---- direct register epilogue ----
    const int erl = warp_r0 + (lane >> 2);       // local row (lo), +8 = hi
    const int ec = (lane & 3) * 2;
    const int glo = row0 + erl, ghi = glo + 8;
    float ss0 = 0.f, ss1 = 0.f;
#pragma unroll
    for (int nt = 0; nt < 7; nt++) {
        int col = (colh * 7 + nt) * 8 + ec;
        float b0 = bias_s[col], b1 = bias_s[col + 1];
        acc[nt][0] += b0; acc[nt][1] += b1;
        acc[nt][2] += b0; acc[nt][3] += b1;
        if (mode == 2) {
            ss0 += acc[nt][0] * acc[nt][0] + acc[nt][1] * acc[nt][1];
            ss1 += acc[nt][2] * acc[nt][2] + acc[nt][3] * acc[nt][3];
        }
    }
    float s0 = 1.f, s1 = 1.f;
    if (mode == 2) {
        // quad reduce (this warp's 56-col partial)
        ss0 += __shfl_xor_sync(0xFFFFFFFFu, ss0, 1);
        ss0 += __shfl_xor_sync(0xFFFFFFFFu, ss0, 2);
        ss1 += __shfl_xor_sync(0xFFFFFFFFu, ss1, 1);
        ss1 += __shfl_xor_sync(0xFFFFFFFFu, ss1, 2);
        if ((lane & 3) == 0) {
            nrm_s[erl * 2 + colh] = ss0;
            nrm_s[(erl + 8) * 2 + colh] = ss1;
        }
        __syncthreads();
        s0 = 1.f / fmaxf(sqrtf(nrm_s[erl * 2] + nrm_s[erl * 2 + 1]), 1e-12f);
        s1 = 1.f / fmaxf(sqrtf(nrm_s[(erl + 8) * 2] + nrm_s[(erl + 8) * 2 + 1]), 1e-12f);
    }
#pragma unroll
    for (int nt = 0; nt < 7; nt++) {
        int col = (colh * 7 + nt) * 8 + ec;
        if (col >= HH) continue;
        float v0 = acc[nt][0], v1 = acc[nt][1], v2 = acc[nt][2], v3 = acc[nt][3];
        if (mode == 3) {
            v0 = fmaxf(v0, 0.f); v1 = fmaxf(v1, 0.f);
            v2 = fmaxf(v2, 0.f); v3 = fmaxf(v3, 0.f);
            uint32_t* zo = (uint32_t*)out;
            if (glo < n) zo[(size_t)glo * ZP + (col >> 1)] = pack_h(v0, v1);
            if (ghi < n) zo[(size_t)ghi * ZP + (col >> 1)] = pack_h(v2, v3);
            continue;
        }
        if (mode == 2) {
            if (glo < n) {
                float2 h0 = *(const float2*)(hres + (size_t)glo * HH + col);
                v0 = h0.x + fmaxf(v0 * s0, 0.f);
                v1 = h0.y + fmaxf(v1 * s0, 0.f);
            }
            if (ghi < n) {
                float2 h1 = *(const float2*)(hres + (size_t)ghi * HH + col);
                v2 = h1.x + fmaxf(v2 * s1, 0.f);
                v3 = h1.y + fmaxf(v3 * s1, 0.f);
            }
        }
        float* o_lo = (mode == 2) ? hres : out;
        if (glo < n) *(float2*)(o_lo + (size_t)glo * HH + col) = make_float2(v0, v1);
        if (ghi < n) *(float2*)(o_lo + (size_t)ghi * HH + col) = make_float2(v2, v3);
        if (outH) {
            uint32_t hp, lp;
            if (glo < n) {
                split2h(v0, v1, hp, lp);
                outH[(size_t)glo * HP + (col >> 1)] = hp;
                outL[(size_t)glo * HP + (col >> 1)] = lp;
            }
            if (ghi < n) {
                split2h(v2, v3, hp, lp);
                outH[(size_t)ghi * HP + (col >> 1)] = hp;
                outL[(size_t)ghi * HP + (col >> 1)] = lp;
            }
        }
    }
}

// ===== mean aggregation over CSR: z packed fp16 (pitch ZP) -> split c (pitch HP)
__global__ void aggregate_kernel(const uint32_t* __restrict__ zp,
                                 uint32_t* __restrict__ ch, uint32_t* __restrict__ cl, int n) {
    int w = (blockIdx.x * blockDim.x + threadIdx.x) >> 5;
    int lane = threadIdx.x & 31;
    if (w >= n || lane >= 27) return;
    int s = g_rowptr[w], e = g_rowptr[w + 1];
    float a0 = 0.f, a1 = 0.f, a2 = 0.f, a3 = 0.f;
    int i = s;
    for (; i + 3 < e; i += 4) {
        int c0 = g_col[i], c1 = g_col[i + 1], c2 = g_col[i + 2], c3 = g_col[i + 3];
        uint2 u0 = ((const uint2*)(zp + (size_t)c0 * ZP))[lane];
        uint2 u1 = ((const uint2*)(zp + (size_t)c1 * ZP))[lane];
        uint2 u2 = ((const uint2*)(zp + (size_t)c2 * ZP))[lane];
        uint2 u3 = ((const uint2*)(zp + (size_t)c3 * ZP))[lane];
        float2 f;
        f = __half22float2(*(__half2*)&u0.x); a0 += f.x; a1 += f.y;
        f = __half22float2(*(__half2*)&u0.y); a2 += f.x; a3 += f.y;
        f = __half22float2(*(__half2*)&u1.x); a0 += f.x; a1 += f.y;
        f = __half22float2(*(__half2*)&u1.y); a2 += f.x; a3 += f.y;
        f = __half22float2(*(__half2*)&u2.x); a0 += f.x; a1 += f.y;
        f = __half22float2(*(__half2*)&u2.y); a2 += f.x; a3 += f.y;
        f = __half22float2(*(__half2*)&u3.x); a0 += f.x; a1 += f.y;
        f = __half22float2(*(__half2*)&u3.y); a2 += f.x; a3 += f.y;
    }
    for (; i < e; i++) {
        uint2 u0 = ((const uint2*)(zp + (size_t)g_col[i] * ZP))[lane];
        float2 f;
        f = __half22float2(*(__half2*)&u0.x); a0 += f.x; a1 += f.y;
        f = __half22float2(*(__half2*)&u0.y); a2 += f.x; a3 += f.y;
    }
    float inv = 1.f / (float)max(e - s, 1);
    uint32_t hp0, lp0, hp1, lp1;
    split2h(a0 * inv, a1 * inv, hp0, lp0);
    split2h(a2 * inv, a3 * inv, hp1, lp1);
    ch[(size_t)w * HP + lane * 2] = hp0;
    ch[(size_t)w * HP + lane * 2 + 1] = hp1;
    cl[(size_t)w * HP + lane * 2] = lp0;
    cl[(size_t)w * HP + lane * 2 + 1] = lp1;
}

// ================= graph readout =================
__global__ void readout_zero_kernel(int g) {
    int i = blockIdx.x * blockDim.x + threadIdx.x;
    if (i < g * HH) g_hg[i] = 0.f;
    if (i < g) g_cnt[i] = 0.f;
}
__global__ void readout_kernel(const float* __restrict__ h, const int* __restrict__ gids, int n) {
    int w = (blockIdx.x * blockDim.x + threadIdx.x) >> 5;
    int lane = threadIdx.x & 31;
    if (w >= n) return;
    int g = gids[w];
    const float* hr = h + (size_t)w * HH;
    atomicAdd(&g_hg[g * HH + lane], hr[lane]);
    atomicAdd(&g_hg[g * HH + lane + 32], hr[lane + 32]);
    atomicAdd(&g_hg[g * HH + lane + 64], hr[lane + 64]);
    if (lane < 12) atomicAdd(&g_hg[g * HH + lane + 96], hr[lane + 96]);
    if (lane == 0) atomicAdd(&g_cnt[g], 1.f);
}
__global__ void finalize_kernel(float* __restrict__ out, int total) {
    int i = blockIdx.x * blockDim.x + threadIdx.x;
    if (i < total) out[i] = g_hg[i] / fmaxf(g_cnt[i / HH], 1.f);
}

// ================= launch =================
extern "C" void kernel_launch(void* const* d_in, const int* in_sizes, int n_in,
                              void* d_out, int out_size) {
    const float* nodes_feat = (const float*)d_in[0];
    const float* W_emb  = (const float*)d_in[4];
    const float* b_emb  = (const float*)d_in[5];
    const float* pool_W = (const float*)d_in[6];
    const float* pool_b = (const float*)d_in[7];
    const float* app_W  = (const float*)d_in[8];
    const float* app_b  = (const float*)d_in[9];
    const int* src  = (const int*)d_in[10];
    const int* dst  = (const int*)d_in[11];
    const int* gids = (const int*)d_in[12];

    const int n = in_sizes[12];
    const int e = in_sizes[10];
    const int in_dim = in_sizes[4] / HH;
    const int n_layers = in_sizes[6] / (HH * HH);
    const int G = out_size / HH;

    float *hP, *zP;
    uint32_t *hhP, *hlP, *chP, *clP, *whP;
    cudaGetSymbolAddress((void**)&hP, g_h);
    cudaGetSymbolAddress((void**)&zP, g_z);
    cudaGetSymbolAddress((void**)&hhP, g_hh);
    cudaGetSymbolAddress((void**)&hlP, g_hl);
    cudaGetSymbolAddress((void**)&chP, g_ch);
    cudaGetSymbolAddress((void**)&clP, g_cl);
    cudaGetSymbolAddress((void**)&whP, g_wh);

    cudaFuncSetAttribute(gemm_tc, cudaFuncAttributeMaxDynamicSharedMemorySize, SM_TOTAL);

    const int KPe = ((in_dim + 63) / 64) * 64;
    const int u_emb = 112 * (KPe >> 1);
    const int u_pool = 112 * 64;
    const int u_app = 112 * 128;
    const int w_total = u_emb + n_layers * (u_pool + u_app);
    const int x_total = n * (KPe >> 1);

    const int gB = (n + 63) / 64;
    int warp_blocks = ((n * 32) + 255) / 256;

    zero_deg_kernel<<<(n + 255) / 256, 256>>>(n);                                   // 1
    prep_w<<<(w_total + 255) / 256, 256>>>(W_emb, in_dim, KPe, pool_W, app_W,
                                           n_layers, w_total);                      // 2
    prep_x<<<(x_total + 255) / 256, 256>>>(nodes_feat, in_dim, KPe, chP, clP,
                                           x_total);                                // 3
    // ---- embedding: h = X @ W_emb + b_emb, capture slot #4 ----
    gemm_tc<<<gB, 256, SM_TOTAL>>>(chP, clP, (const uint32_t*)0, (const uint32_t*)0,
                                   KPe >> 6, KPe >> 1,
                                   whP, KPe >> 1,
                                   b_emb, hP, (float*)0, hhP, hlP,
                                   n, KPe, 0);                                      // 4
    // ---- CSR by dst ----
    hist_kernel<<<(e + 255) / 256, 256>>>(dst, e);
    int nb = (n + SC_CH - 1) / SC_CH;
    scan1_kernel<<<nb, SC_T>>>(n);
    scan2_kernel<<<1, 256>>>(nb);
    scan3_kernel<<<(n + 255) / 256, 256>>>(n);
    fillcsr_kernel<<<(e + 255) / 256, 256>>>(src, dst, e);

    for (int l = 0; l < n_layers; l++) {
        const float* pb = pool_b + (size_t)l * HH;
        const float* ab = app_b + (size_t)l * HH;
        const uint32_t* pWh = whP + u_emb + l * u_pool;
        const uint32_t* aWh = whP + u_emb + n_layers * u_pool + l * u_app;

        // z = relu(h @ pool_W + pool_b) -> packed fp16, pitch ZP
        gemm_tc<<<gB, 256, SM_TOTAL>>>(hhP, hlP, (const uint32_t*)0, (const uint32_t*)0,
                                       2, HP,
                                       pWh, 64,
                                       pb, zP, (float*)0, (uint32_t*)0, (uint32_t*)0,
                                       n, 128, 3);
        // c = mean_{u in N(v)} z[u]
        aggregate_kernel<<<warp_blocks, 256>>>((const uint32_t*)zP, chP, clP, n);
        // h += relu(l2norm([h|c] @ app_W + app_b))
        int last = (l == n_layers - 1);
        gemm_tc<<<gB, 256, SM_TOTAL>>>(hhP, hlP, chP, clP,
                                       2, HP,
                                       aWh, 128,
                                       ab, (float*)0, hP,
                                       last ? (uint32_t*)0 : hhP,
                                       last ? (uint32_t*)0 : hlP,
                                       n, 256, 2);
    }

    // ---- readout ----
    readout_zero_kernel<<<(G * HH + 255) / 256, 256>>>(G);
    readout_kernel<<<warp_blocks, 256>>>(hP, gids, n);
    finalize_kernel<<<(out_size + 255) / 256, 256>>>((float*)d_out, out_size);
}